// round 10
// baseline (speedup 1.0000x reference)
#include <cuda_runtime.h>
#include <cuda_bf16.h>
#include <math.h>
#include <stdint.h>

#define Bb   4
#define Nn   1024
#define Dd   512
#define Hh   8
#define DHh  64
#define HIDn 32

// ---------------------------------------------------------------------------
// Static scratch (allocation-free per harness rules)
// ---------------------------------------------------------------------------
__device__ float g_q[Bb*Hh*Nn*DHh];               // pre-scaled by dh^-0.5
__device__ float g_k[Bb*Hh*Nn*DHh];
__device__ float g_v[Bb*Hh*Nn*DHh];
__device__ float g_bias[(size_t)Bb*Hh*Nn*Nn];     // [B,H,N,N] additive bias
__device__ float g_att[Bb*Nn*Dd];                 // [B,N,D] attention output
__device__ float g_U[Bb*Nn*HIDn];                 // coords @ w1  [B,N,32]

// bf16 hi/lo split operands for tensor-core GEMMs
__device__ __nv_bfloat16 g_xh[4096*512],  g_xl[4096*512];    // x            [M,K]
__device__ __nv_bfloat16 g_wth[1536*512], g_wtl[1536*512];   // qkv_w^T      [N,K]
__device__ __nv_bfloat16 g_ath[4096*512], g_atl[4096*512];   // att          [M,K]
__device__ __nv_bfloat16 g_owth[512*512], g_owtl[512*512];   // out_w^T      [N,K]

// ---------------------------------------------------------------------------
// Packed fp32x2 FMA (Blackwell FFMA2; PTX 8.6, sm_100+ family-wide)
// ---------------------------------------------------------------------------
__device__ __forceinline__ float2 ffma2(float2 a, float2 b, float2 c) {
    float2 d;
    asm("fma.rn.f32x2 %0, %1, %2, %3;"
        : "=l"(*(unsigned long long*)&d)
        : "l"(*(unsigned long long*)&a),
          "l"(*(unsigned long long*)&b),
          "l"(*(unsigned long long*)&c));
    return d;
}

// ---------------------------------------------------------------------------
// mma.sync / ldmatrix helpers (baseline PTX, compile on plain sm_103)
// ---------------------------------------------------------------------------
__device__ __forceinline__ uint32_t smem_u32(const void* p) {
    uint32_t a;
    asm("{ .reg .u64 t; cvta.to.shared.u64 t, %1; cvt.u32.u64 %0, t; }" : "=r"(a) : "l"(p));
    return a;
}
__device__ __forceinline__ void ldsm4(uint32_t r[4], uint32_t addr) {
    asm volatile("ldmatrix.sync.aligned.m8n8.x4.shared.b16 {%0,%1,%2,%3}, [%4];"
        : "=r"(r[0]), "=r"(r[1]), "=r"(r[2]), "=r"(r[3]) : "r"(addr));
}
__device__ __forceinline__ void mma16816(float c[4], const uint32_t a[4], const uint32_t b[2]) {
    asm volatile("mma.sync.aligned.m16n8k16.row.col.f32.bf16.bf16.f32 "
        "{%0,%1,%2,%3}, {%4,%5,%6,%7}, {%8,%9}, {%0,%1,%2,%3};"
        : "+f"(c[0]), "+f"(c[1]), "+f"(c[2]), "+f"(c[3])
        : "r"(a[0]), "r"(a[1]), "r"(a[2]), "r"(a[3]), "r"(b[0]), "r"(b[1]));
}

#define TP 40   // smem tile pitch in bf16 (80B) -> ldmatrix conflict-free

// ---------------------------------------------------------------------------
// hi/lo bf16 split kernels
// ---------------------------------------------------------------------------
__device__ __forceinline__ void split_store4(float4 v, __nv_bfloat16* hi,
                                             __nv_bfloat16* lo, size_t i4) {
    float a[4] = {v.x, v.y, v.z, v.w};
    __nv_bfloat16 h[4], l[4];
    #pragma unroll
    for (int j = 0; j < 4; j++) {
        h[j] = __float2bfloat16_rn(a[j]);
        l[j] = __float2bfloat16_rn(a[j] - __bfloat162float(h[j]));
    }
    ((__nv_bfloat162*)hi)[2*i4]   = __halves2bfloat162(h[0], h[1]);
    ((__nv_bfloat162*)hi)[2*i4+1] = __halves2bfloat162(h[2], h[3]);
    ((__nv_bfloat162*)lo)[2*i4]   = __halves2bfloat162(l[0], l[1]);
    ((__nv_bfloat162*)lo)[2*i4+1] = __halves2bfloat162(l[2], l[3]);
}

__global__ __launch_bounds__(256) void k_split_x(const float4* __restrict__ src) {
    size_t i = (size_t)blockIdx.x * 256 + threadIdx.x;
    split_store4(src[i], g_xh, g_xl, i);
}
__global__ __launch_bounds__(256) void k_split_att() {
    size_t i = (size_t)blockIdx.x * 256 + threadIdx.x;
    split_store4(((const float4*)g_att)[i], g_ath, g_atl, i);
}

// Transpose + split: src fp32 [K, N] -> dst bf16 [N, K]. which: 0=qkv_w, 1=out_w
__global__ void k_splitT(const float* __restrict__ src, int K, int N, int which) {
    __shared__ float ts[32][33];
    int kk = blockIdx.y * 32 + threadIdx.y;
    int nn = blockIdx.x * 32 + threadIdx.x;
    ts[threadIdx.y][threadIdx.x] = src[(size_t)kk * N + nn];
    __syncthreads();
    int on = blockIdx.x * 32 + threadIdx.y;
    int ok = blockIdx.y * 32 + threadIdx.x;
    float v = ts[threadIdx.x][threadIdx.y];
    __nv_bfloat16 h = __float2bfloat16_rn(v);
    __nv_bfloat16 l = __float2bfloat16_rn(v - __bfloat162float(h));
    __nv_bfloat16* hd = which ? g_owth : g_wth;
    __nv_bfloat16* ld = which ? g_owtl : g_wtl;
    hd[(size_t)on * K + ok] = h;
    ld[(size_t)on * K + ok] = l;
}

// ---------------------------------------------------------------------------
// HMMA bf16x3 mainloop (unchanged from R8)
// ---------------------------------------------------------------------------
struct SmemTiles {
    __nv_bfloat16 Ah[128 * TP];
    __nv_bfloat16 Al[128 * TP];
    __nv_bfloat16 Bh[128 * TP];
    __nv_bfloat16 Bl[128 * TP];
};

__device__ __forceinline__ void gmem_to_tile(__nv_bfloat16* dst,
                                             const __nv_bfloat16* __restrict__ src,
                                             int row0, int k0, int tid) {
    #pragma unroll
    for (int i = 0; i < 2; i++) {
        int idx = tid + (i << 8);
        int rr = idx >> 2, sg = idx & 3;
        uint4 v = *(const uint4*)((const char*)src + ((size_t)(row0 + rr) * 512 + k0) * 2 + sg * 16);
        *(uint4*)((char*)dst + (rr * TP) * 2 + sg * 16) = v;
    }
}

__device__ __forceinline__ void mma_all(float acc[4][4][4],
                                        const uint32_t a[4][4],
                                        const uint32_t b[4][2]) {
    #pragma unroll
    for (int mt = 0; mt < 4; mt++)
        #pragma unroll
        for (int nt = 0; nt < 4; nt++)
            mma16816(acc[mt][nt], a[mt], b[nt]);
}

__device__ __forceinline__ void load_afrag(uint32_t a[4][4], uint32_t base_u32,
                                           int wyBase, int kb, int lane) {
    int r  = wyBase + (lane & 15);
    int kc = (kb << 4) + ((lane >> 4) << 3);
    uint32_t addr = base_u32 + (uint32_t)(r * TP + kc) * 2;
    #pragma unroll
    for (int mt = 0; mt < 4; mt++)
        ldsm4(a[mt], addr + mt * (16 * TP * 2));
}

__device__ __forceinline__ void load_bfrag(uint32_t b[4][2], uint32_t base_u32,
                                           int wxBase, int kb, int lane) {
    int n  = wxBase + (((lane >> 4) & 1) << 3) + (lane & 7);
    int kc = (kb << 4) + (((lane >> 3) & 1) << 3);
    uint32_t addr = base_u32 + (uint32_t)(n * TP + kc) * 2;
    #pragma unroll
    for (int np = 0; np < 2; np++) {
        uint32_t t4[4];
        ldsm4(t4, addr + np * (16 * TP * 2));
        b[np * 2 + 0][0] = t4[0]; b[np * 2 + 0][1] = t4[1];
        b[np * 2 + 1][0] = t4[2]; b[np * 2 + 1][1] = t4[3];
    }
}

__device__ __forceinline__ void hmma_mainloop(
    float acc[4][4][4], SmemTiles* sm,
    const __nv_bfloat16* Ah, const __nv_bfloat16* Al,
    const __nv_bfloat16* Bh, const __nv_bfloat16* Bl,
    int m0, int n0, int tid)
{
    int lane = tid & 31, wid = tid >> 5;
    int wyBase = (wid >> 2) * 64, wxBase = (wid & 3) * 32;
    uint32_t uAh = smem_u32(sm->Ah), uAl = smem_u32(sm->Al);
    uint32_t uBh = smem_u32(sm->Bh), uBl = smem_u32(sm->Bl);

    for (int k0 = 0; k0 < 512; k0 += 32) {
        gmem_to_tile(sm->Ah, Ah, m0, k0, tid);
        gmem_to_tile(sm->Al, Al, m0, k0, tid);
        gmem_to_tile(sm->Bh, Bh, n0, k0, tid);
        gmem_to_tile(sm->Bl, Bl, n0, k0, tid);
        __syncthreads();
        #pragma unroll
        for (int kb = 0; kb < 2; kb++) {
            uint32_t a[4][4], b[4][2];
            load_afrag(a, uAh, wyBase, kb, lane);
            load_bfrag(b, uBl, wxBase, kb, lane);
            mma_all(acc, a, b);
            load_bfrag(b, uBh, wxBase, kb, lane);
            mma_all(acc, a, b);
            load_afrag(a, uAl, wyBase, kb, lane);
            mma_all(acc, a, b);
        }
        __syncthreads();
    }
}

// ---------------------------------------------------------------------------
// K1: QKV projection on HMMA.
// ---------------------------------------------------------------------------
__global__ __launch_bounds__(256, 2) void k_qkv_mma() {
    __shared__ SmemTiles sm;
    int tid = threadIdx.x;
    int n0 = blockIdx.x << 7, m0 = blockIdx.y << 7;

    float acc[4][4][4];
    #pragma unroll
    for (int mt = 0; mt < 4; mt++)
        #pragma unroll
        for (int nt = 0; nt < 4; nt++)
            acc[mt][nt][0] = acc[mt][nt][1] = acc[mt][nt][2] = acc[mt][nt][3] = 0.0f;

    hmma_mainloop(acc, &sm, g_xh, g_xl, g_wth, g_wtl, m0, n0, tid);

    int lane = tid & 31, wid = tid >> 5;
    int wyBase = (wid >> 2) * 64, wxBase = (wid & 3) * 32;
    int g = lane >> 2, tig = lane & 3;

    int sec = n0 >> 9;
    float s = (sec == 0) ? 0.125f : 1.0f;
    float* dst = (sec == 0) ? g_q : (sec == 1) ? g_k : g_v;

    #pragma unroll
    for (int mt = 0; mt < 4; mt++) {
        #pragma unroll
        for (int nt = 0; nt < 4; nt++) {
            int col = n0 + wxBase + (nt << 3) + (tig << 1);
            int h = (col & 511) >> 6, e = col & 63;
            #pragma unroll
            for (int half = 0; half < 2; half++) {
                int row = m0 + wyBase + (mt << 4) + g + (half << 3);
                int b = row >> 10, n = row & 1023;
                float* pd = dst + ((size_t)((b << 3) + h) * Nn + n) * DHh + e;
                *(float2*)pd = make_float2(acc[mt][nt][half * 2] * s,
                                           acc[mt][nt][half * 2 + 1] * s);
            }
        }
    }
}

// ---------------------------------------------------------------------------
// K4: output projection on HMMA.
// ---------------------------------------------------------------------------
__global__ __launch_bounds__(256, 2) void k_out_mma(const float* __restrict__ bias,
                                                    float* __restrict__ out) {
    __shared__ SmemTiles sm;
    int tid = threadIdx.x;
    int n0 = blockIdx.x << 7, m0 = blockIdx.y << 7;

    float acc[4][4][4];
    #pragma unroll
    for (int mt = 0; mt < 4; mt++)
        #pragma unroll
        for (int nt = 0; nt < 4; nt++)
            acc[mt][nt][0] = acc[mt][nt][1] = acc[mt][nt][2] = acc[mt][nt][3] = 0.0f;

    hmma_mainloop(acc, &sm, g_ath, g_atl, g_owth, g_owtl, m0, n0, tid);

    int lane = tid & 31, wid = tid >> 5;
    int wyBase = (wid >> 2) * 64, wxBase = (wid & 3) * 32;
    int g = lane >> 2, tig = lane & 3;

    #pragma unroll
    for (int mt = 0; mt < 4; mt++) {
        #pragma unroll
        for (int nt = 0; nt < 4; nt++) {
            int col = n0 + wxBase + (nt << 3) + (tig << 1);
            float2 bv = *(const float2*)(bias + col);
            #pragma unroll
            for (int half = 0; half < 2; half++) {
                int row = m0 + wyBase + (mt << 4) + g + (half << 3);
                *(float2*)(out + (size_t)row * Dd + col) =
                    make_float2(acc[mt][nt][half * 2] + bv.x,
                                acc[mt][nt][half * 2 + 1] + bv.y);
            }
        }
    }
}

// ---------------------------------------------------------------------------
// K2a: U = coords @ w1  (tiny precompute; [B,N,32])
// ---------------------------------------------------------------------------
__global__ __launch_bounds__(256) void k_proj(const float* __restrict__ coords,
                                              const float* __restrict__ w1) {
    int idx = blockIdx.x * 256 + threadIdx.x;       // 131072 outputs
    int row = idx >> 5, m = idx & 31;
    float c0 = coords[row * 3 + 0];
    float c1 = coords[row * 3 + 1];
    float c2 = coords[row * 3 + 2];
    g_U[idx] = fmaf(c0, w1[m], fmaf(c1, w1[32 + m], c2 * w1[64 + m]));
}

// ---------------------------------------------------------------------------
// K2b: bias MLP v2. hs = (U_i + b1) - U_j; g = exact GELU(hs);
// bias[h] += g * w2[m][h] via packed FFMA2. Once per (b,i,j), all 8 heads.
// ---------------------------------------------------------------------------
__global__ __launch_bounds__(256) void k_bias(const float* __restrict__ b1,
                                              const float* __restrict__ w2,
                                              const float* __restrict__ b2) {
    __shared__ float  sUi[32 * 33];
    __shared__ float  sUj[32 * 33];
    __shared__ float2 sw2[HIDn * 4];   // [m][head-pair]
    __shared__ float2 sb2[4];

    int b  = blockIdx.z;
    int i0 = blockIdx.y << 5;
    int j0 = blockIdx.x << 5;
    int tid = threadIdx.x;

    {   // load U tiles (32 rows x 32 m each), fold b1 into the i side
        int r = tid >> 3, m4 = (tid & 7) << 2;
        float4 ui = *(const float4*)(g_U + ((size_t)(b << 10) + i0 + r) * HIDn + m4);
        float4 bb = *(const float4*)(b1 + m4);
        sUi[r * 33 + m4 + 0] = ui.x + bb.x;
        sUi[r * 33 + m4 + 1] = ui.y + bb.y;
        sUi[r * 33 + m4 + 2] = ui.z + bb.z;
        sUi[r * 33 + m4 + 3] = ui.w + bb.w;
        float4 uj = *(const float4*)(g_U + ((size_t)(b << 10) + j0 + r) * HIDn + m4);
        sUj[r * 33 + m4 + 0] = uj.x;
        sUj[r * 33 + m4 + 1] = uj.y;
        sUj[r * 33 + m4 + 2] = uj.z;
        sUj[r * 33 + m4 + 3] = uj.w;
    }
    if (tid < 128) {
        int m = tid >> 2, hp = tid & 3;
        sw2[m * 4 + hp] = *(const float2*)(w2 + m * Hh + (hp << 1));
    }
    if (tid < 4) sb2[tid] = *(const float2*)(b2 + (tid << 1));
    __syncthreads();

    #pragma unroll
    for (int q = 0; q < 4; q++) {
        int p = tid + (q << 8);
        int i = p >> 5, j = p & 31;
        const float* ui = sUi + i * 33;
        const float* uj = sUj + j * 33;
        float2 acc[4] = {sb2[0], sb2[1], sb2[2], sb2[3]};
        #pragma unroll
        for (int m = 0; m < HIDn; m++) {
            float hs = ui[m] - uj[m];
            float g  = 0.5f * hs * (1.0f + erff(hs * 0.70710678118654752f));
            float2 gg = make_float2(g, g);
            acc[0] = ffma2(gg, sw2[m * 4 + 0], acc[0]);
            acc[1] = ffma2(gg, sw2[m * 4 + 1], acc[1]);
            acc[2] = ffma2(gg, sw2[m * 4 + 2], acc[2]);
            acc[3] = ffma2(gg, sw2[m * 4 + 3], acc[3]);
        }
        size_t base = ((size_t)((b * Hh) << 10) + i0 + i) * Nn + j0 + j;
        float av[8] = {acc[0].x, acc[0].y, acc[1].x, acc[1].y,
                       acc[2].x, acc[2].y, acc[3].x, acc[3].y};
        #pragma unroll
        for (int h = 0; h < Hh; h++)
            g_bias[base + (size_t)h * (Nn * Nn)] = av[h];
    }
}

// ---------------------------------------------------------------------------
// K3: fused attention with packed FFMA2 inner products.
// ---------------------------------------------------------------------------
#define ATTN_SMEM ((64*132 + 64*68 + 64*68 + 128*68) * 4)

__global__ __launch_bounds__(256, 2) void k_attn(const unsigned char* __restrict__ mask) {
    extern __shared__ float fsm[];
    float* Qs = fsm;                 // [k=64][i=128] pitch 132 (transposed Q)
    float* Ks = Qs + 64 * 132;       // [k=64][j=64]  pitch 68  (transposed K)
    float* Vs = Ks + 64 * 68;        // [j=64][e=64]  pitch 68
    float* Ps = Vs + 64 * 68;        // [i=128][j=64] pitch 68

    int tid = threadIdx.x, tx = tid & 15, ty = tid >> 4;
    int bh = blockIdx.y, i0 = blockIdx.x << 7;
    int b = bh >> 3, h = bh & 7;

    const float* Q    = g_q + (size_t)bh * Nn * DHh;
    const float* Kg   = g_k + (size_t)bh * Nn * DHh;
    const float* Vg   = g_v + (size_t)bh * Nn * DHh;
    const float* Bias = g_bias + (size_t)bh * Nn * Nn;
    const unsigned char* mrow = mask + ((size_t)b << 10);

    #pragma unroll
    for (int it = 0; it < 8; it++) {
        int lin = tid + (it << 8);
        int m = lin >> 4, kq = (lin & 15) << 2;
        float4 v = *(const float4*)(Q + (size_t)(i0 + m) * DHh + kq);
        Qs[(kq + 0) * 132 + m] = v.x;
        Qs[(kq + 1) * 132 + m] = v.y;
        Qs[(kq + 2) * 132 + m] = v.z;
        Qs[(kq + 3) * 132 + m] = v.w;
    }

    float m_i[8], l_i[8];
    float2 o2[8][2];                 // (o0,o1),(o2,o3) per row
    #pragma unroll
    for (int i = 0; i < 8; i++) {
        m_i[i] = -1e30f; l_i[i] = 0.0f;
        o2[i][0] = make_float2(0.f, 0.f);
        o2[i][1] = make_float2(0.f, 0.f);
    }

    for (int j0 = 0; j0 < Nn; j0 += 64) {
        __syncthreads();
        #pragma unroll
        for (int it = 0; it < 4; it++) {
            int lin = tid + (it << 8);
            int j = lin >> 4, kq = (lin & 15) << 2;
            float4 kv = *(const float4*)(Kg + (size_t)(j0 + j) * DHh + kq);
            Ks[(kq + 0) * 68 + j] = kv.x;
            Ks[(kq + 1) * 68 + j] = kv.y;
            Ks[(kq + 2) * 68 + j] = kv.z;
            Ks[(kq + 3) * 68 + j] = kv.w;
            *(float4*)(Vs + j * 68 + kq) = *(const float4*)(Vg + (size_t)(j0 + j) * DHh + kq);
        }
        __syncthreads();

        // S = Q @ K^T with FFMA2: s2[ip][j] = (s[2ip][j], s[2ip+1][j])
        float2 s2[4][4];
        #pragma unroll
        for (int ip = 0; ip < 4; ip++)
            #pragma unroll
            for (int j = 0; j < 4; j++) s2[ip][j] = make_float2(0.f, 0.f);
        #pragma unroll
        for (int k = 0; k < 64; k++) {
            float4 a0 = *(const float4*)(Qs + k * 132 + (ty << 3));
            float4 a1 = *(const float4*)(Qs + k * 132 + (ty << 3) + 4);
            float4 bq = *(const float4*)(Ks + k * 68 + (tx << 2));
            float2 ap[4] = {{a0.x, a0.y}, {a0.z, a0.w}, {a1.x, a1.y}, {a1.z, a1.w}};
            float2 bd[4] = {{bq.x, bq.x}, {bq.y, bq.y}, {bq.z, bq.z}, {bq.w, bq.w}};
            #pragma unroll
            for (int ip = 0; ip < 4; ip++)
                #pragma unroll
                for (int j = 0; j < 4; j++)
                    s2[ip][j] = ffma2(ap[ip], bd[j], s2[ip][j]);
        }
        float s[8][4];
        #pragma unroll
        for (int ip = 0; ip < 4; ip++)
            #pragma unroll
            for (int j = 0; j < 4; j++) {
                s[2 * ip][j]     = s2[ip][j].x;
                s[2 * ip + 1][j] = s2[ip][j].y;
            }

        uchar4 mk = *(const uchar4*)(mrow + j0 + (tx << 2));
        #pragma unroll
        for (int i = 0; i < 8; i++) {
            int gi = i0 + (ty << 3) + i;
            float4 bv = *(const float4*)(Bias + (size_t)gi * Nn + j0 + (tx << 2));
            s[i][0] += bv.x; s[i][1] += bv.y; s[i][2] += bv.z; s[i][3] += bv.w;
            if (mk.x) s[i][0] = -1e30f;
            if (mk.y) s[i][1] = -1e30f;
            if (mk.z) s[i][2] = -1e30f;
            if (mk.w) s[i][3] = -1e30f;
        }

        #pragma unroll
        for (int i = 0; i < 8; i++) {
            float mx = fmaxf(fmaxf(s[i][0], s[i][1]), fmaxf(s[i][2], s[i][3]));
            #pragma unroll
            for (int off = 8; off; off >>= 1)
                mx = fmaxf(mx, __shfl_xor_sync(0xFFFFFFFFu, mx, off));
            float mn = fmaxf(m_i[i], mx);
            float f  = __expf(m_i[i] - mn);
            m_i[i] = mn;
            float p0 = __expf(s[i][0] - mn);
            float p1 = __expf(s[i][1] - mn);
            float p2 = __expf(s[i][2] - mn);
            float p3 = __expf(s[i][3] - mn);
            l_i[i] = l_i[i] * f + (p0 + p1 + p2 + p3);
            o2[i][0].x *= f; o2[i][0].y *= f;
            o2[i][1].x *= f; o2[i][1].y *= f;
            int il = (ty << 3) + i;
            *(float4*)(Ps + il * 68 + (tx << 2)) = make_float4(p0, p1, p2, p3);
        }
        __syncthreads();

        // O += P @ V with FFMA2
        #pragma unroll
        for (int jg = 0; jg < 16; jg++) {
            float4 vv0 = *(const float4*)(Vs + (jg * 4 + 0) * 68 + (tx << 2));
            float4 vv1 = *(const float4*)(Vs + (jg * 4 + 1) * 68 + (tx << 2));
            float4 vv2 = *(const float4*)(Vs + (jg * 4 + 2) * 68 + (tx << 2));
            float4 vv3 = *(const float4*)(Vs + (jg * 4 + 3) * 68 + (tx << 2));
            float2 v0a = {vv0.x, vv0.y}, v0b = {vv0.z, vv0.w};
            float2 v1a = {vv1.x, vv1.y}, v1b = {vv1.z, vv1.w};
            float2 v2a = {vv2.x, vv2.y}, v2b = {vv2.z, vv2.w};
            float2 v3a = {vv3.x, vv3.y}, v3b = {vv3.z, vv3.w};
            #pragma unroll
            for (int i = 0; i < 8; i++) {
                float4 pv = *(const float4*)(Ps + ((ty << 3) + i) * 68 + (jg << 2));
                float2 px = {pv.x, pv.x}, py = {pv.y, pv.y};
                float2 pz = {pv.z, pv.z}, pw = {pv.w, pv.w};
                o2[i][0] = ffma2(px, v0a, o2[i][0]);
                o2[i][1] = ffma2(px, v0b, o2[i][1]);
                o2[i][0] = ffma2(py, v1a, o2[i][0]);
                o2[i][1] = ffma2(py, v1b, o2[i][1]);
                o2[i][0] = ffma2(pz, v2a, o2[i][0]);
                o2[i][1] = ffma2(pz, v2b, o2[i][1]);
                o2[i][0] = ffma2(pw, v3a, o2[i][0]);
                o2[i][1] = ffma2(pw, v3b, o2[i][1]);
            }
        }
    }

    #pragma unroll
    for (int i = 0; i < 8; i++) {
        float lt = l_i[i];
        #pragma unroll
        for (int off = 8; off; off >>= 1)
            lt += __shfl_xor_sync(0xFFFFFFFFu, lt, off);
        float inv = __frcp_rn(lt);
        int gi = i0 + (ty << 3) + i;
        *(float4*)(g_att + ((size_t)(b << 10) + gi) * Dd + h * DHh + (tx << 2)) =
            make_float4(o2[i][0].x * inv, o2[i][0].y * inv,
                        o2[i][1].x * inv, o2[i][1].y * inv);
    }
}

// ---------------------------------------------------------------------------
// Launch
// ---------------------------------------------------------------------------
extern "C" void kernel_launch(void* const* d_in, const int* in_sizes, int n_in,
                              void* d_out, int out_size) {
    const float*         x      = (const float*)d_in[0];
    const float*         coords = (const float*)d_in[1];
    const unsigned char* mask   = (const unsigned char*)d_in[2];
    const float*         qkv_w  = (const float*)d_in[3];
    const float*         out_w  = (const float*)d_in[4];
    const float*         out_b  = (const float*)d_in[5];
    const float*         w1     = (const float*)d_in[6];
    const float*         b1     = (const float*)d_in[7];
    const float*         w2     = (const float*)d_in[8];
    const float*         b2     = (const float*)d_in[9];
    float*               out    = (float*)d_out;

    static int attrs_set = 0;
    if (!attrs_set) {
        cudaFuncSetAttribute(k_attn, cudaFuncAttributeMaxDynamicSharedMemorySize, ATTN_SMEM);
        attrs_set = 1;
    }

    k_split_x  <<<2048, 256>>>((const float4*)x);
    k_splitT   <<<dim3(48, 16), dim3(32, 32)>>>(qkv_w, Dd, 3 * Dd, 0);
    k_qkv_mma  <<<dim3(12, 32), 256>>>();
    k_proj     <<<512, 256>>>(coords, w1);
    k_bias     <<<dim3(32, 32, Bb), 256>>>(b1, w2, b2);
    k_attn     <<<dim3(8, 32), 256, ATTN_SMEM>>>(mask);
    k_split_att<<<2048, 256>>>();
    k_splitT   <<<dim3(16, 16), dim3(32, 32)>>>(out_w, Dd, Dd, 1);
    k_out_mma  <<<dim3(4, 32), 256>>>(out_b, out);
}

// round 11
// speedup vs baseline: 1.2107x; 1.2107x over previous
#include <cuda_runtime.h>
#include <cuda_bf16.h>
#include <math.h>
#include <stdint.h>

#define Bb   4
#define Nn   1024
#define Dd   512
#define Hh   8
#define DHh  64
#define HIDn 32

// ---------------------------------------------------------------------------
// Static scratch (allocation-free per harness rules)
// ---------------------------------------------------------------------------
__device__ float g_bias[(size_t)Bb*Hh*Nn*Nn];     // [B,H,N,N] additive bias
__device__ float g_U[Bb*Nn*HIDn];                 // coords @ w1  [B,N,32]

// bf16 hi/lo operands
__device__ __nv_bfloat16 g_xh[4096*512],  g_xl[4096*512];    // x          [M,K]
__device__ __nv_bfloat16 g_wth[1536*512], g_wtl[1536*512];   // qkv_w^T    [N,K]
__device__ __nv_bfloat16 g_ath[4096*512], g_atl[4096*512];   // att        [M,K]
__device__ __nv_bfloat16 g_owth[512*512], g_owtl[512*512];   // out_w^T    [N,K]
__device__ __nv_bfloat16 g_qh[Bb*Hh*Nn*DHh], g_ql[Bb*Hh*Nn*DHh];  // q (x0.125)
__device__ __nv_bfloat16 g_kh[Bb*Hh*Nn*DHh], g_kl[Bb*Hh*Nn*DHh];
__device__ __nv_bfloat16 g_vh[Bb*Hh*Nn*DHh], g_vl[Bb*Hh*Nn*DHh];

// ---------------------------------------------------------------------------
// Packed fp32x2 FMA (used only in k_bias where operands pack cleanly)
// ---------------------------------------------------------------------------
__device__ __forceinline__ float2 ffma2(float2 a, float2 b, float2 c) {
    float2 d;
    asm("fma.rn.f32x2 %0, %1, %2, %3;"
        : "=l"(*(unsigned long long*)&d)
        : "l"(*(unsigned long long*)&a),
          "l"(*(unsigned long long*)&b),
          "l"(*(unsigned long long*)&c));
    return d;
}

// ---------------------------------------------------------------------------
// mma.sync / ldmatrix helpers (baseline PTX, compile on plain sm_103)
// ---------------------------------------------------------------------------
__device__ __forceinline__ uint32_t smem_u32(const void* p) {
    uint32_t a;
    asm("{ .reg .u64 t; cvta.to.shared.u64 t, %1; cvt.u32.u64 %0, t; }" : "=r"(a) : "l"(p));
    return a;
}
__device__ __forceinline__ void ldsm4(uint32_t r[4], uint32_t addr) {
    asm volatile("ldmatrix.sync.aligned.m8n8.x4.shared.b16 {%0,%1,%2,%3}, [%4];"
        : "=r"(r[0]), "=r"(r[1]), "=r"(r[2]), "=r"(r[3]) : "r"(addr));
}
__device__ __forceinline__ void ldsm4t(uint32_t r[4], uint32_t addr) {
    asm volatile("ldmatrix.sync.aligned.m8n8.x4.trans.shared.b16 {%0,%1,%2,%3}, [%4];"
        : "=r"(r[0]), "=r"(r[1]), "=r"(r[2]), "=r"(r[3]) : "r"(addr));
}
__device__ __forceinline__ void mma16816(float c[4], const uint32_t a[4], const uint32_t b[2]) {
    asm volatile("mma.sync.aligned.m16n8k16.row.col.f32.bf16.bf16.f32 "
        "{%0,%1,%2,%3}, {%4,%5,%6,%7}, {%8,%9}, {%0,%1,%2,%3};"
        : "+f"(c[0]), "+f"(c[1]), "+f"(c[2]), "+f"(c[3])
        : "r"(a[0]), "r"(a[1]), "r"(a[2]), "r"(a[3]), "r"(b[0]), "r"(b[1]));
}

#define TP 40   // GEMM smem tile pitch (bf16)

// ---------------------------------------------------------------------------
// hi/lo bf16 split kernels (input x + weight transposes)
// ---------------------------------------------------------------------------
__global__ __launch_bounds__(256) void k_split_x(const float4* __restrict__ src) {
    size_t i = (size_t)blockIdx.x * 256 + threadIdx.x;
    float4 v = src[i];
    float a[4] = {v.x, v.y, v.z, v.w};
    __nv_bfloat16 h[4], l[4];
    #pragma unroll
    for (int j = 0; j < 4; j++) {
        h[j] = __float2bfloat16_rn(a[j]);
        l[j] = __float2bfloat16_rn(a[j] - __bfloat162float(h[j]));
    }
    ((__nv_bfloat162*)g_xh)[2*i]   = __halves2bfloat162(h[0], h[1]);
    ((__nv_bfloat162*)g_xh)[2*i+1] = __halves2bfloat162(h[2], h[3]);
    ((__nv_bfloat162*)g_xl)[2*i]   = __halves2bfloat162(l[0], l[1]);
    ((__nv_bfloat162*)g_xl)[2*i+1] = __halves2bfloat162(l[2], l[3]);
}

__global__ void k_splitT(const float* __restrict__ src, int K, int N, int which) {
    __shared__ float ts[32][33];
    int kk = blockIdx.y * 32 + threadIdx.y;
    int nn = blockIdx.x * 32 + threadIdx.x;
    ts[threadIdx.y][threadIdx.x] = src[(size_t)kk * N + nn];
    __syncthreads();
    int on = blockIdx.x * 32 + threadIdx.y;
    int ok = blockIdx.y * 32 + threadIdx.x;
    float v = ts[threadIdx.x][threadIdx.y];
    __nv_bfloat16 h = __float2bfloat16_rn(v);
    __nv_bfloat16 l = __float2bfloat16_rn(v - __bfloat162float(h));
    __nv_bfloat16* hd = which ? g_owth : g_wth;
    __nv_bfloat16* ld = which ? g_owtl : g_wtl;
    hd[(size_t)on * K + ok] = h;
    ld[(size_t)on * K + ok] = l;
}

// ---------------------------------------------------------------------------
// HMMA bf16x3 GEMM mainloop (validated in R8/R9)
// ---------------------------------------------------------------------------
struct SmemTiles {
    __nv_bfloat16 Ah[128 * TP];
    __nv_bfloat16 Al[128 * TP];
    __nv_bfloat16 Bh[128 * TP];
    __nv_bfloat16 Bl[128 * TP];
};

__device__ __forceinline__ void gmem_to_tile(__nv_bfloat16* dst,
                                             const __nv_bfloat16* __restrict__ src,
                                             int row0, int k0, int tid) {
    #pragma unroll
    for (int i = 0; i < 2; i++) {
        int idx = tid + (i << 8);
        int rr = idx >> 2, sg = idx & 3;
        uint4 v = *(const uint4*)((const char*)src + ((size_t)(row0 + rr) * 512 + k0) * 2 + sg * 16);
        *(uint4*)((char*)dst + (rr * TP) * 2 + sg * 16) = v;
    }
}

__device__ __forceinline__ void mma_all(float acc[4][4][4],
                                        const uint32_t a[4][4],
                                        const uint32_t b[4][2]) {
    #pragma unroll
    for (int mt = 0; mt < 4; mt++)
        #pragma unroll
        for (int nt = 0; nt < 4; nt++)
            mma16816(acc[mt][nt], a[mt], b[nt]);
}

__device__ __forceinline__ void load_afrag(uint32_t a[4][4], uint32_t base_u32,
                                           int wyBase, int kb, int lane) {
    int r  = wyBase + (lane & 15);
    int kc = (kb << 4) + ((lane >> 4) << 3);
    uint32_t addr = base_u32 + (uint32_t)(r * TP + kc) * 2;
    #pragma unroll
    for (int mt = 0; mt < 4; mt++)
        ldsm4(a[mt], addr + mt * (16 * TP * 2));
}

__device__ __forceinline__ void load_bfrag(uint32_t b[4][2], uint32_t base_u32,
                                           int wxBase, int kb, int lane) {
    int n  = wxBase + (((lane >> 4) & 1) << 3) + (lane & 7);
    int kc = (kb << 4) + (((lane >> 3) & 1) << 3);
    uint32_t addr = base_u32 + (uint32_t)(n * TP + kc) * 2;
    #pragma unroll
    for (int np = 0; np < 2; np++) {
        uint32_t t4[4];
        ldsm4(t4, addr + np * (16 * TP * 2));
        b[np * 2 + 0][0] = t4[0]; b[np * 2 + 0][1] = t4[1];
        b[np * 2 + 1][0] = t4[2]; b[np * 2 + 1][1] = t4[3];
    }
}

__device__ __forceinline__ void hmma_mainloop(
    float acc[4][4][4], SmemTiles* sm,
    const __nv_bfloat16* Ah, const __nv_bfloat16* Al,
    const __nv_bfloat16* Bh, const __nv_bfloat16* Bl,
    int m0, int n0, int tid)
{
    int lane = tid & 31, wid = tid >> 5;
    int wyBase = (wid >> 2) * 64, wxBase = (wid & 3) * 32;
    uint32_t uAh = smem_u32(sm->Ah), uAl = smem_u32(sm->Al);
    uint32_t uBh = smem_u32(sm->Bh), uBl = smem_u32(sm->Bl);

    for (int k0 = 0; k0 < 512; k0 += 32) {
        gmem_to_tile(sm->Ah, Ah, m0, k0, tid);
        gmem_to_tile(sm->Al, Al, m0, k0, tid);
        gmem_to_tile(sm->Bh, Bh, n0, k0, tid);
        gmem_to_tile(sm->Bl, Bl, n0, k0, tid);
        __syncthreads();
        #pragma unroll
        for (int kb = 0; kb < 2; kb++) {
            uint32_t a[4][4], b[4][2];
            load_afrag(a, uAh, wyBase, kb, lane);
            load_bfrag(b, uBl, wxBase, kb, lane);
            mma_all(acc, a, b);
            load_bfrag(b, uBh, wxBase, kb, lane);
            mma_all(acc, a, b);
            load_afrag(a, uAl, wyBase, kb, lane);
            mma_all(acc, a, b);
        }
        __syncthreads();
    }
}

// ---------------------------------------------------------------------------
// K1: QKV projection on HMMA; epilogue writes q/k/v as bf16 hi/lo (q x0.125).
// ---------------------------------------------------------------------------
__global__ __launch_bounds__(256, 2) void k_qkv_mma() {
    __shared__ SmemTiles sm;
    int tid = threadIdx.x;
    int n0 = blockIdx.x << 7, m0 = blockIdx.y << 7;

    float acc[4][4][4];
    #pragma unroll
    for (int mt = 0; mt < 4; mt++)
        #pragma unroll
        for (int nt = 0; nt < 4; nt++)
            acc[mt][nt][0] = acc[mt][nt][1] = acc[mt][nt][2] = acc[mt][nt][3] = 0.0f;

    hmma_mainloop(acc, &sm, g_xh, g_xl, g_wth, g_wtl, m0, n0, tid);

    int lane = tid & 31, wid = tid >> 5;
    int wyBase = (wid >> 2) * 64, wxBase = (wid & 3) * 32;
    int g = lane >> 2, tig = lane & 3;

    int sec = n0 >> 9;
    float s = (sec == 0) ? 0.125f : 1.0f;
    __nv_bfloat16* dh = (sec == 0) ? g_qh : (sec == 1) ? g_kh : g_vh;
    __nv_bfloat16* dl = (sec == 0) ? g_ql : (sec == 1) ? g_kl : g_vl;

    #pragma unroll
    for (int mt = 0; mt < 4; mt++) {
        #pragma unroll
        for (int nt = 0; nt < 4; nt++) {
            int col = n0 + wxBase + (nt << 3) + (tig << 1);
            int h = (col & 511) >> 6, e = col & 63;
            #pragma unroll
            for (int half = 0; half < 2; half++) {
                int row = m0 + wyBase + (mt << 4) + g + (half << 3);
                int b = row >> 10, n = row & 1023;
                float v0 = acc[mt][nt][half * 2]     * s;
                float v1 = acc[mt][nt][half * 2 + 1] * s;
                __nv_bfloat162 hp = __float22bfloat162_rn(make_float2(v0, v1));
                __nv_bfloat162 lp = __float22bfloat162_rn(make_float2(
                    v0 - __bfloat162float(hp.x), v1 - __bfloat162float(hp.y)));
                size_t off = ((size_t)((b << 3) + h) * Nn + n) * DHh + e;
                *(__nv_bfloat162*)(dh + off) = hp;
                *(__nv_bfloat162*)(dl + off) = lp;
            }
        }
    }
}

// ---------------------------------------------------------------------------
// K4: output projection on HMMA. out = att @ out_w + out_b
// ---------------------------------------------------------------------------
__global__ __launch_bounds__(256, 2) void k_out_mma(const float* __restrict__ bias,
                                                    float* __restrict__ out) {
    __shared__ SmemTiles sm;
    int tid = threadIdx.x;
    int n0 = blockIdx.x << 7, m0 = blockIdx.y << 7;

    float acc[4][4][4];
    #pragma unroll
    for (int mt = 0; mt < 4; mt++)
        #pragma unroll
        for (int nt = 0; nt < 4; nt++)
            acc[mt][nt][0] = acc[mt][nt][1] = acc[mt][nt][2] = acc[mt][nt][3] = 0.0f;

    hmma_mainloop(acc, &sm, g_ath, g_atl, g_owth, g_owtl, m0, n0, tid);

    int lane = tid & 31, wid = tid >> 5;
    int wyBase = (wid >> 2) * 64, wxBase = (wid & 3) * 32;
    int g = lane >> 2, tig = lane & 3;

    #pragma unroll
    for (int mt = 0; mt < 4; mt++) {
        #pragma unroll
        for (int nt = 0; nt < 4; nt++) {
            int col = n0 + wxBase + (nt << 3) + (tig << 1);
            float2 bv = *(const float2*)(bias + col);
            #pragma unroll
            for (int half = 0; half < 2; half++) {
                int row = m0 + wyBase + (mt << 4) + g + (half << 3);
                *(float2*)(out + (size_t)row * Dd + col) =
                    make_float2(acc[mt][nt][half * 2] + bv.x,
                                acc[mt][nt][half * 2 + 1] + bv.y);
            }
        }
    }
}

// ---------------------------------------------------------------------------
// K2a: U = coords @ w1
// ---------------------------------------------------------------------------
__global__ __launch_bounds__(256) void k_proj(const float* __restrict__ coords,
                                              const float* __restrict__ w1) {
    int idx = blockIdx.x * 256 + threadIdx.x;
    int row = idx >> 5, m = idx & 31;
    float c0 = coords[row * 3 + 0];
    float c1 = coords[row * 3 + 1];
    float c2 = coords[row * 3 + 2];
    g_U[idx] = fmaf(c0, w1[m], fmaf(c1, w1[32 + m], c2 * w1[64 + m]));
}

// ---------------------------------------------------------------------------
// K2b: bias MLP v2 (R10 version — algebraic restructure)
// ---------------------------------------------------------------------------
__global__ __launch_bounds__(256) void k_bias(const float* __restrict__ b1,
                                              const float* __restrict__ w2,
                                              const float* __restrict__ b2) {
    __shared__ float  sUi[32 * 33];
    __shared__ float  sUj[32 * 33];
    __shared__ float2 sw2[HIDn * 4];
    __shared__ float2 sb2[4];

    int b  = blockIdx.z;
    int i0 = blockIdx.y << 5;
    int j0 = blockIdx.x << 5;
    int tid = threadIdx.x;

    {
        int r = tid >> 3, m4 = (tid & 7) << 2;
        float4 ui = *(const float4*)(g_U + ((size_t)(b << 10) + i0 + r) * HIDn + m4);
        float4 bb = *(const float4*)(b1 + m4);
        sUi[r * 33 + m4 + 0] = ui.x + bb.x;
        sUi[r * 33 + m4 + 1] = ui.y + bb.y;
        sUi[r * 33 + m4 + 2] = ui.z + bb.z;
        sUi[r * 33 + m4 + 3] = ui.w + bb.w;
        float4 uj = *(const float4*)(g_U + ((size_t)(b << 10) + j0 + r) * HIDn + m4);
        sUj[r * 33 + m4 + 0] = uj.x;
        sUj[r * 33 + m4 + 1] = uj.y;
        sUj[r * 33 + m4 + 2] = uj.z;
        sUj[r * 33 + m4 + 3] = uj.w;
    }
    if (tid < 128) {
        int m = tid >> 2, hp = tid & 3;
        sw2[m * 4 + hp] = *(const float2*)(w2 + m * Hh + (hp << 1));
    }
    if (tid < 4) sb2[tid] = *(const float2*)(b2 + (tid << 1));
    __syncthreads();

    #pragma unroll
    for (int q = 0; q < 4; q++) {
        int p = tid + (q << 8);
        int i = p >> 5, j = p & 31;
        const float* ui = sUi + i * 33;
        const float* uj = sUj + j * 33;
        float2 acc[4] = {sb2[0], sb2[1], sb2[2], sb2[3]};
        #pragma unroll
        for (int m = 0; m < HIDn; m++) {
            float hs = ui[m] - uj[m];
            float g  = 0.5f * hs * (1.0f + erff(hs * 0.70710678118654752f));
            float2 gg = make_float2(g, g);
            acc[0] = ffma2(gg, sw2[m * 4 + 0], acc[0]);
            acc[1] = ffma2(gg, sw2[m * 4 + 1], acc[1]);
            acc[2] = ffma2(gg, sw2[m * 4 + 2], acc[2]);
            acc[3] = ffma2(gg, sw2[m * 4 + 3], acc[3]);
        }
        size_t base = ((size_t)((b * Hh) << 10) + i0 + i) * Nn + j0 + j;
        float av[8] = {acc[0].x, acc[0].y, acc[1].x, acc[1].y,
                       acc[2].x, acc[2].y, acc[3].x, acc[3].y};
        #pragma unroll
        for (int h = 0; h < Hh; h++)
            g_bias[base + (size_t)h * (Nn * Nn)] = av[h];
    }
}

// ---------------------------------------------------------------------------
// K3: HMMA flash attention. CTA = 128 i-rows x one (b,h); 8 warps, each owns
// 16 rows (softmax fully warp-local). j-tiles of 64. bf16x3 for S and PV.
// smem: Kh,Kl,Vh,Vl (64x64, pitch 72) + Ph,Pl (128x64, pitch 72).
// ---------------------------------------------------------------------------
#define APITCH 72                      // bf16 pitch (144B rows)
#define AOFF_KH 0
#define AOFF_KL 9216
#define AOFF_VH 18432
#define AOFF_VL 27648
#define AOFF_PH 36864
#define AOFF_PL 55296
#define AT_SMEM 73728

__global__ __launch_bounds__(256) void k_attn_mma(const unsigned char* __restrict__ mask) {
    extern __shared__ char smx[];
    uint32_t sb = smem_u32(smx);
    int tid = threadIdx.x, lane = tid & 31, w = tid >> 5;
    int g = lane >> 2, tig = lane & 3;
    int bh = blockIdx.y, i0 = blockIdx.x << 7;
    int b = bh >> 3, h = bh & 7;

    const __nv_bfloat16* Qh = g_qh + (size_t)bh * Nn * DHh;
    const __nv_bfloat16* Ql = g_ql + (size_t)bh * Nn * DHh;
    const __nv_bfloat16* Kh = g_kh + (size_t)bh * Nn * DHh;
    const __nv_bfloat16* Kl = g_kl + (size_t)bh * Nn * DHh;
    const __nv_bfloat16* Vh = g_vh + (size_t)bh * Nn * DHh;
    const __nv_bfloat16* Vl = g_vl + (size_t)bh * Nn * DHh;
    const unsigned char* mrow = mask + ((size_t)b << 10);
    int r0 = i0 + w * 16 + g;                         // this lane's row pair
    const float* br0 = g_bias + (size_t)bh * Nn * Nn + (size_t)r0 * Nn;
    const float* br1 = br0 + 8 * Nn;

    // --- stage Q fragments into registers (hi then lo, via P buffer) ---
    uint32_t qfh[4][4], qfl[4][4];
    #pragma unroll
    for (int pass = 0; pass < 2; pass++) {
        const __nv_bfloat16* src = pass ? Ql : Qh;
        int row = tid >> 1, off = (tid & 1) * 64;
        const uint4* s4 = (const uint4*)((const char*)(src + (size_t)(i0 + row) * DHh) + off);
        uint4* d4 = (uint4*)(smx + AOFF_PH + row * 144 + off);
        d4[0] = s4[0]; d4[1] = s4[1]; d4[2] = s4[2]; d4[3] = s4[3];
        __syncthreads();
        uint32_t base = sb + AOFF_PH + (uint32_t)((w * 16 + (lane & 15)) * 144 + ((lane >> 4) << 4));
        #pragma unroll
        for (int ks = 0; ks < 4; ks++)
            ldsm4(pass ? qfl[ks] : qfh[ks], base + ks * 32);
        __syncthreads();
    }

    float o[8][4];
    #pragma unroll
    for (int nt = 0; nt < 8; nt++)
        o[nt][0] = o[nt][1] = o[nt][2] = o[nt][3] = 0.0f;
    float m0 = -1e30f, m1 = -1e30f, l0 = 0.0f, l1 = 0.0f;

    for (int jt = 0; jt < 16; jt++) {
        int j0 = jt << 6;
        __syncthreads();                 // prior tile's V reads done
        {   // load K/V hi/lo tiles: 64 rows x 128B each
            int row = tid >> 2, off = (tid & 3) * 32;
            size_t go = (size_t)(j0 + row) * DHh;
            const char* skh = (const char*)(Kh + go) + off;
            const char* skl = (const char*)(Kl + go) + off;
            const char* svh = (const char*)(Vh + go) + off;
            const char* svl = (const char*)(Vl + go) + off;
            char* d = smx + row * 144 + off;
            *(uint4*)(d + AOFF_KH)      = *(const uint4*)skh;
            *(uint4*)(d + AOFF_KH + 16) = *(const uint4*)(skh + 16);
            *(uint4*)(d + AOFF_KL)      = *(const uint4*)skl;
            *(uint4*)(d + AOFF_KL + 16) = *(const uint4*)(skl + 16);
            *(uint4*)(d + AOFF_VH)      = *(const uint4*)svh;
            *(uint4*)(d + AOFF_VH + 16) = *(const uint4*)(svh + 16);
            *(uint4*)(d + AOFF_VL)      = *(const uint4*)svl;
            *(uint4*)(d + AOFF_VL + 16) = *(const uint4*)(svl + 16);
        }

        // init S accumulators with bias (MMA accumulates on top)
        float s[8][4];
        #pragma unroll
        for (int nt = 0; nt < 8; nt++) {
            int col = j0 + (nt << 3) + (tig << 1);
            float2 b0 = *(const float2*)(br0 + col);
            float2 b1 = *(const float2*)(br1 + col);
            s[nt][0] = b0.x; s[nt][1] = b0.y;
            s[nt][2] = b1.x; s[nt][3] = b1.y;
        }
        __syncthreads();                 // K/V tiles visible

        // S += Q K^T (bf16x3)
        #pragma unroll
        for (int ks = 0; ks < 4; ks++) {
            #pragma unroll
            for (int ng = 0; ng < 4; ng++) {
                int n  = (ng << 4) + (((lane >> 4) & 1) << 3) + (lane & 7);
                int kc = (ks << 4) + (((lane >> 3) & 1) << 3);
                uint32_t off = (uint32_t)(n * 144 + kc * 2);
                uint32_t th[4], tl[4];
                ldsm4(th, sb + AOFF_KH + off);
                ldsm4(tl, sb + AOFF_KL + off);
                uint32_t bh0[2] = {th[0], th[1]}, bh1[2] = {th[2], th[3]};
                uint32_t bl0[2] = {tl[0], tl[1]}, bl1[2] = {tl[2], tl[3]};
                mma16816(s[ng * 2 + 0], qfh[ks], bh0);
                mma16816(s[ng * 2 + 1], qfh[ks], bh1);
                mma16816(s[ng * 2 + 0], qfh[ks], bl0);
                mma16816(s[ng * 2 + 1], qfh[ks], bl1);
                mma16816(s[ng * 2 + 0], qfl[ks], bh0);
                mma16816(s[ng * 2 + 1], qfl[ks], bh1);
            }
        }

        // mask
        #pragma unroll
        for (int nt = 0; nt < 8; nt++) {
            int col = j0 + (nt << 3) + (tig << 1);
            uchar2 mk = *(const uchar2*)(mrow + col);
            if (mk.x) { s[nt][0] = -1e30f; s[nt][2] = -1e30f; }
            if (mk.y) { s[nt][1] = -1e30f; s[nt][3] = -1e30f; }
        }

        // online softmax (warp-local rows; quad reduction)
        float mx0 = -1e30f, mx1 = -1e30f;
        #pragma unroll
        for (int nt = 0; nt < 8; nt++) {
            mx0 = fmaxf(mx0, fmaxf(s[nt][0], s[nt][1]));
            mx1 = fmaxf(mx1, fmaxf(s[nt][2], s[nt][3]));
        }
        mx0 = fmaxf(mx0, __shfl_xor_sync(0xFFFFFFFFu, mx0, 1));
        mx0 = fmaxf(mx0, __shfl_xor_sync(0xFFFFFFFFu, mx0, 2));
        mx1 = fmaxf(mx1, __shfl_xor_sync(0xFFFFFFFFu, mx1, 1));
        mx1 = fmaxf(mx1, __shfl_xor_sync(0xFFFFFFFFu, mx1, 2));
        float mn0 = fmaxf(m0, mx0), f0 = __expf(m0 - mn0); m0 = mn0;
        float mn1 = fmaxf(m1, mx1), f1 = __expf(m1 - mn1); m1 = mn1;

        float ps0 = 0.0f, ps1 = 0.0f;
        int prow0 = (w * 16 + g) * 144;
        #pragma unroll
        for (int nt = 0; nt < 8; nt++) {
            float p00 = __expf(s[nt][0] - mn0);
            float p01 = __expf(s[nt][1] - mn0);
            float p10 = __expf(s[nt][2] - mn1);
            float p11 = __expf(s[nt][3] - mn1);
            ps0 += p00 + p01;
            ps1 += p10 + p11;
            int cb = ((nt << 3) + (tig << 1)) * 2;
            __nv_bfloat162 h0 = __float22bfloat162_rn(make_float2(p00, p01));
            __nv_bfloat162 l0p = __float22bfloat162_rn(make_float2(
                p00 - __bfloat162float(h0.x), p01 - __bfloat162float(h0.y)));
            __nv_bfloat162 h1 = __float22bfloat162_rn(make_float2(p10, p11));
            __nv_bfloat162 l1p = __float22bfloat162_rn(make_float2(
                p10 - __bfloat162float(h1.x), p11 - __bfloat162float(h1.y)));
            *(__nv_bfloat162*)(smx + AOFF_PH + prow0 + cb)        = h0;
            *(__nv_bfloat162*)(smx + AOFF_PL + prow0 + cb)        = l0p;
            *(__nv_bfloat162*)(smx + AOFF_PH + prow0 + 8*144 + cb) = h1;
            *(__nv_bfloat162*)(smx + AOFF_PL + prow0 + 8*144 + cb) = l1p;
        }
        l0 = l0 * f0 + ps0;
        l1 = l1 * f1 + ps1;
        #pragma unroll
        for (int nt = 0; nt < 8; nt++) {
            o[nt][0] *= f0; o[nt][1] *= f0;
            o[nt][2] *= f1; o[nt][3] *= f1;
        }
        __syncwarp();                    // P rows are warp-private

        // O += P V (bf16x3); V B-frags via ldmatrix.trans from [j][e]
        uint32_t abase = sb + (uint32_t)((w * 16 + (lane & 15)) * 144 + ((lane >> 4) << 4));
        #pragma unroll
        for (int ks = 0; ks < 4; ks++) {
            uint32_t ph[4], pl[4];
            ldsm4(ph, abase + AOFF_PH + ks * 32);
            ldsm4(pl, abase + AOFF_PL + ks * 32);
            #pragma unroll
            for (int eg = 0; eg < 4; eg++) {
                uint32_t voff = (uint32_t)(((ks << 4) + (lane & 15)) * 144 +
                                           (((eg << 4) + ((lane >> 4) << 3)) * 2));
                uint32_t th[4], tl[4];
                ldsm4t(th, sb + AOFF_VH + voff);
                ldsm4t(tl, sb + AOFF_VL + voff);
                uint32_t bh0[2] = {th[0], th[1]}, bh1[2] = {th[2], th[3]};
                uint32_t bl0[2] = {tl[0], tl[1]}, bl1[2] = {tl[2], tl[3]};
                mma16816(o[eg * 2 + 0], ph, bh0);
                mma16816(o[eg * 2 + 1], ph, bh1);
                mma16816(o[eg * 2 + 0], ph, bl0);
                mma16816(o[eg * 2 + 1], ph, bl1);
                mma16816(o[eg * 2 + 0], pl, bh0);
                mma16816(o[eg * 2 + 1], pl, bh1);
            }
        }
    }

    // finalize: divide by row sums, write att as bf16 hi/lo [b, i, h*64+e]
    l0 += __shfl_xor_sync(0xFFFFFFFFu, l0, 1);
    l0 += __shfl_xor_sync(0xFFFFFFFFu, l0, 2);
    l1 += __shfl_xor_sync(0xFFFFFFFFu, l1, 1);
    l1 += __shfl_xor_sync(0xFFFFFFFFu, l1, 2);
    float inv0 = __frcp_rn(l0), inv1 = __frcp_rn(l1);
    #pragma unroll
    for (int nt = 0; nt < 8; nt++) {
        int e = (nt << 3) + (tig << 1);
        #pragma unroll
        for (int half = 0; half < 2; half++) {
            float inv = half ? inv1 : inv0;
            int row = r0 + (half << 3);
            float v0 = o[nt][half * 2]     * inv;
            float v1 = o[nt][half * 2 + 1] * inv;
            __nv_bfloat162 hp = __float22bfloat162_rn(make_float2(v0, v1));
            __nv_bfloat162 lp = __float22bfloat162_rn(make_float2(
                v0 - __bfloat162float(hp.x), v1 - __bfloat162float(hp.y)));
            size_t off = ((size_t)(b << 10) + row) * Dd + h * DHh + e;
            *(__nv_bfloat162*)(g_ath + off) = hp;
            *(__nv_bfloat162*)(g_atl + off) = lp;
        }
    }
}

// ---------------------------------------------------------------------------
// Launch
// ---------------------------------------------------------------------------
extern "C" void kernel_launch(void* const* d_in, const int* in_sizes, int n_in,
                              void* d_out, int out_size) {
    const float*         x      = (const float*)d_in[0];
    const float*         coords = (const float*)d_in[1];
    const unsigned char* mask   = (const unsigned char*)d_in[2];
    const float*         qkv_w  = (const float*)d_in[3];
    const float*         out_w  = (const float*)d_in[4];
    const float*         out_b  = (const float*)d_in[5];
    const float*         w1     = (const float*)d_in[6];
    const float*         b1     = (const float*)d_in[7];
    const float*         w2     = (const float*)d_in[8];
    const float*         b2     = (const float*)d_in[9];
    float*               out    = (float*)d_out;

    static int attrs_set = 0;
    if (!attrs_set) {
        cudaFuncSetAttribute(k_attn_mma, cudaFuncAttributeMaxDynamicSharedMemorySize, AT_SMEM);
        attrs_set = 1;
    }

    k_split_x <<<2048, 256>>>((const float4*)x);
    k_splitT  <<<dim3(48, 16), dim3(32, 32)>>>(qkv_w, Dd, 3 * Dd, 0);
    k_qkv_mma <<<dim3(12, 32), 256>>>();
    k_proj    <<<512, 256>>>(coords, w1);
    k_bias    <<<dim3(32, 32, Bb), 256>>>(b1, w2, b2);
    k_attn_mma<<<dim3(8, 32), 256, AT_SMEM>>>(mask);
    k_splitT  <<<dim3(16, 16), dim3(32, 32)>>>(out_w, Dd, Dd, 1);
    k_out_mma <<<dim3(4, 32), 256>>>(out_b, out);
}

// round 12
// speedup vs baseline: 1.2492x; 1.0318x over previous
#include <cuda_runtime.h>
#include <cuda_bf16.h>
#include <math.h>
#include <stdint.h>

#define Bb   4
#define Nn   1024
#define Dd   512
#define Hh   8
#define DHh  64
#define HIDn 32

// ---------------------------------------------------------------------------
// Static scratch (allocation-free per harness rules)
// ---------------------------------------------------------------------------
__device__ float g_bias[(size_t)Bb*Hh*Nn*Nn];     // [B,H,N,N] additive bias
__device__ float g_U[Bb*Nn*HIDn];                 // coords @ w1  [B,N,32]

// bf16 hi/lo operands
__device__ __nv_bfloat16 g_xh[4096*512],  g_xl[4096*512];    // x          [M,K]
__device__ __nv_bfloat16 g_wth[1536*512], g_wtl[1536*512];   // qkv_w^T    [N,K]
__device__ __nv_bfloat16 g_ath[4096*512], g_atl[4096*512];   // att        [M,K]
__device__ __nv_bfloat16 g_owth[512*512], g_owtl[512*512];   // out_w^T    [N,K]
__device__ __nv_bfloat16 g_qh[Bb*Hh*Nn*DHh], g_ql[Bb*Hh*Nn*DHh];  // q (x0.125)
__device__ __nv_bfloat16 g_kh[Bb*Hh*Nn*DHh], g_kl[Bb*Hh*Nn*DHh];
__device__ __nv_bfloat16 g_vh[Bb*Hh*Nn*DHh], g_vl[Bb*Hh*Nn*DHh];

// ---------------------------------------------------------------------------
// Packed fp32x2 FMA (k_bias only — operands pack cleanly there)
// ---------------------------------------------------------------------------
__device__ __forceinline__ float2 ffma2(float2 a, float2 b, float2 c) {
    float2 d;
    asm("fma.rn.f32x2 %0, %1, %2, %3;"
        : "=l"(*(unsigned long long*)&d)
        : "l"(*(unsigned long long*)&a),
          "l"(*(unsigned long long*)&b),
          "l"(*(unsigned long long*)&c));
    return d;
}

// ---------------------------------------------------------------------------
// mma.sync / ldmatrix / cp.async helpers (baseline PTX, OK on plain sm_103)
// ---------------------------------------------------------------------------
__device__ __forceinline__ uint32_t smem_u32(const void* p) {
    uint32_t a;
    asm("{ .reg .u64 t; cvta.to.shared.u64 t, %1; cvt.u32.u64 %0, t; }" : "=r"(a) : "l"(p));
    return a;
}
__device__ __forceinline__ void ldsm4(uint32_t r[4], uint32_t addr) {
    asm volatile("ldmatrix.sync.aligned.m8n8.x4.shared.b16 {%0,%1,%2,%3}, [%4];"
        : "=r"(r[0]), "=r"(r[1]), "=r"(r[2]), "=r"(r[3]) : "r"(addr));
}
__device__ __forceinline__ void ldsm4t(uint32_t r[4], uint32_t addr) {
    asm volatile("ldmatrix.sync.aligned.m8n8.x4.trans.shared.b16 {%0,%1,%2,%3}, [%4];"
        : "=r"(r[0]), "=r"(r[1]), "=r"(r[2]), "=r"(r[3]) : "r"(addr));
}
__device__ __forceinline__ void mma16816(float c[4], const uint32_t a[4], const uint32_t b[2]) {
    asm volatile("mma.sync.aligned.m16n8k16.row.col.f32.bf16.bf16.f32 "
        "{%0,%1,%2,%3}, {%4,%5,%6,%7}, {%8,%9}, {%0,%1,%2,%3};"
        : "+f"(c[0]), "+f"(c[1]), "+f"(c[2]), "+f"(c[3])
        : "r"(a[0]), "r"(a[1]), "r"(a[2]), "r"(a[3]), "r"(b[0]), "r"(b[1]));
}
__device__ __forceinline__ void cp16(uint32_t dst, const void* src) {
    asm volatile("cp.async.ca.shared.global [%0], [%1], 16;" :: "r"(dst), "l"(src));
}
#define CP_COMMIT() asm volatile("cp.async.commit_group;" ::: "memory")
#define CP_WAIT(n)  asm volatile("cp.async.wait_group %0;" :: "n"(n) : "memory")

#define TP 40   // GEMM smem tile pitch (bf16)

// ---------------------------------------------------------------------------
// hi/lo bf16 split kernels (input x + weight transposes)
// ---------------------------------------------------------------------------
__global__ __launch_bounds__(256) void k_split_x(const float4* __restrict__ src) {
    size_t i = (size_t)blockIdx.x * 256 + threadIdx.x;
    float4 v = src[i];
    float a[4] = {v.x, v.y, v.z, v.w};
    __nv_bfloat16 h[4], l[4];
    #pragma unroll
    for (int j = 0; j < 4; j++) {
        h[j] = __float2bfloat16_rn(a[j]);
        l[j] = __float2bfloat16_rn(a[j] - __bfloat162float(h[j]));
    }
    ((__nv_bfloat162*)g_xh)[2*i]   = __halves2bfloat162(h[0], h[1]);
    ((__nv_bfloat162*)g_xh)[2*i+1] = __halves2bfloat162(h[2], h[3]);
    ((__nv_bfloat162*)g_xl)[2*i]   = __halves2bfloat162(l[0], l[1]);
    ((__nv_bfloat162*)g_xl)[2*i+1] = __halves2bfloat162(l[2], l[3]);
}

__global__ void k_splitT(const float* __restrict__ src, int K, int N, int which) {
    __shared__ float ts[32][33];
    int kk = blockIdx.y * 32 + threadIdx.y;
    int nn = blockIdx.x * 32 + threadIdx.x;
    ts[threadIdx.y][threadIdx.x] = src[(size_t)kk * N + nn];
    __syncthreads();
    int on = blockIdx.x * 32 + threadIdx.y;
    int ok = blockIdx.y * 32 + threadIdx.x;
    float v = ts[threadIdx.x][threadIdx.y];
    __nv_bfloat16 h = __float2bfloat16_rn(v);
    __nv_bfloat16 l = __float2bfloat16_rn(v - __bfloat162float(h));
    __nv_bfloat16* hd = which ? g_owth : g_wth;
    __nv_bfloat16* ld = which ? g_owtl : g_wtl;
    hd[(size_t)on * K + ok] = h;
    ld[(size_t)on * K + ok] = l;
}

// ---------------------------------------------------------------------------
// HMMA bf16x3 GEMM mainloop — cp.async double-buffered.
// Dynamic smem: 2 buffers x 4 tiles x 128 rows x TP bf16 = 81920 bytes.
// ---------------------------------------------------------------------------
#define TILE_B   (128 * TP * 2)          // 10240 bytes per tile
#define BUF_B    (4 * TILE_B)            // 40960 bytes per buffer
#define GEMM_SMEM (2 * BUF_B)            // 81920

__device__ __forceinline__ void cp_tile(uint32_t dst, const __nv_bfloat16* __restrict__ src,
                                        int row0, int k0, int tid) {
    #pragma unroll
    for (int i = 0; i < 2; i++) {
        int idx = tid + (i << 8);
        int rr = idx >> 2, sg = idx & 3;
        cp16(dst + (uint32_t)((rr * TP) * 2 + sg * 16),
             (const char*)src + ((size_t)(row0 + rr) * 512 + k0) * 2 + sg * 16);
    }
}

__device__ __forceinline__ void issue_chunk(uint32_t sb, int buf,
    const __nv_bfloat16* Ah, const __nv_bfloat16* Al,
    const __nv_bfloat16* Bh, const __nv_bfloat16* Bl,
    int m0, int n0, int k0, int tid)
{
    uint32_t b = sb + buf * BUF_B;
    cp_tile(b + 0 * TILE_B, Ah, m0, k0, tid);
    cp_tile(b + 1 * TILE_B, Al, m0, k0, tid);
    cp_tile(b + 2 * TILE_B, Bh, n0, k0, tid);
    cp_tile(b + 3 * TILE_B, Bl, n0, k0, tid);
    CP_COMMIT();
}

__device__ __forceinline__ void mma_all(float acc[4][4][4],
                                        const uint32_t a[4][4],
                                        const uint32_t b[4][2]) {
    #pragma unroll
    for (int mt = 0; mt < 4; mt++)
        #pragma unroll
        for (int nt = 0; nt < 4; nt++)
            mma16816(acc[mt][nt], a[mt], b[nt]);
}

__device__ __forceinline__ void load_afrag(uint32_t a[4][4], uint32_t base_u32,
                                           int wyBase, int kb, int lane) {
    int r  = wyBase + (lane & 15);
    int kc = (kb << 4) + ((lane >> 4) << 3);
    uint32_t addr = base_u32 + (uint32_t)(r * TP + kc) * 2;
    #pragma unroll
    for (int mt = 0; mt < 4; mt++)
        ldsm4(a[mt], addr + mt * (16 * TP * 2));
}

__device__ __forceinline__ void load_bfrag(uint32_t b[4][2], uint32_t base_u32,
                                           int wxBase, int kb, int lane) {
    int n  = wxBase + (((lane >> 4) & 1) << 3) + (lane & 7);
    int kc = (kb << 4) + (((lane >> 3) & 1) << 3);
    uint32_t addr = base_u32 + (uint32_t)(n * TP + kc) * 2;
    #pragma unroll
    for (int np = 0; np < 2; np++) {
        uint32_t t4[4];
        ldsm4(t4, addr + np * (16 * TP * 2));
        b[np * 2 + 0][0] = t4[0]; b[np * 2 + 0][1] = t4[1];
        b[np * 2 + 1][0] = t4[2]; b[np * 2 + 1][1] = t4[3];
    }
}

__device__ __forceinline__ void hmma_mainloop(
    float acc[4][4][4], char* smem,
    const __nv_bfloat16* Ah, const __nv_bfloat16* Al,
    const __nv_bfloat16* Bh, const __nv_bfloat16* Bl,
    int m0, int n0, int tid)
{
    int lane = tid & 31, wid = tid >> 5;
    int wyBase = (wid >> 2) * 64, wxBase = (wid & 3) * 32;
    uint32_t sb = smem_u32(smem);

    issue_chunk(sb, 0, Ah, Al, Bh, Bl, m0, n0, 0, tid);
    #pragma unroll 1
    for (int c = 0; c < 16; c++) {
        if (c < 15) {
            issue_chunk(sb, (c + 1) & 1, Ah, Al, Bh, Bl, m0, n0, (c + 1) * 32, tid);
            CP_WAIT(1);
        } else {
            CP_WAIT(0);
        }
        __syncthreads();
        uint32_t base = sb + (c & 1) * BUF_B;
        uint32_t uAh = base, uAl = base + TILE_B;
        uint32_t uBh = base + 2 * TILE_B, uBl = base + 3 * TILE_B;
        #pragma unroll
        for (int kb = 0; kb < 2; kb++) {
            uint32_t a[4][4], b[4][2];
            load_afrag(a, uAh, wyBase, kb, lane);
            load_bfrag(b, uBl, wxBase, kb, lane);
            mma_all(acc, a, b);
            load_bfrag(b, uBh, wxBase, kb, lane);
            mma_all(acc, a, b);
            load_afrag(a, uAl, wyBase, kb, lane);
            mma_all(acc, a, b);
        }
        __syncthreads();
    }
}

// ---------------------------------------------------------------------------
// K1: QKV projection on HMMA; epilogue writes q/k/v as bf16 hi/lo (q x0.125).
// ---------------------------------------------------------------------------
__global__ __launch_bounds__(256, 2) void k_qkv_mma() {
    extern __shared__ char smg[];
    int tid = threadIdx.x;
    int n0 = blockIdx.x << 7, m0 = blockIdx.y << 7;

    float acc[4][4][4];
    #pragma unroll
    for (int mt = 0; mt < 4; mt++)
        #pragma unroll
        for (int nt = 0; nt < 4; nt++)
            acc[mt][nt][0] = acc[mt][nt][1] = acc[mt][nt][2] = acc[mt][nt][3] = 0.0f;

    hmma_mainloop(acc, smg, g_xh, g_xl, g_wth, g_wtl, m0, n0, tid);

    int lane = tid & 31, wid = tid >> 5;
    int wyBase = (wid >> 2) * 64, wxBase = (wid & 3) * 32;
    int g = lane >> 2, tig = lane & 3;

    int sec = n0 >> 9;
    float s = (sec == 0) ? 0.125f : 1.0f;
    __nv_bfloat16* dh = (sec == 0) ? g_qh : (sec == 1) ? g_kh : g_vh;
    __nv_bfloat16* dl = (sec == 0) ? g_ql : (sec == 1) ? g_kl : g_vl;

    #pragma unroll
    for (int mt = 0; mt < 4; mt++) {
        #pragma unroll
        for (int nt = 0; nt < 4; nt++) {
            int col = n0 + wxBase + (nt << 3) + (tig << 1);
            int h = (col & 511) >> 6, e = col & 63;
            #pragma unroll
            for (int half = 0; half < 2; half++) {
                int row = m0 + wyBase + (mt << 4) + g + (half << 3);
                int b = row >> 10, n = row & 1023;
                float v0 = acc[mt][nt][half * 2]     * s;
                float v1 = acc[mt][nt][half * 2 + 1] * s;
                __nv_bfloat162 hp = __float22bfloat162_rn(make_float2(v0, v1));
                __nv_bfloat162 lp = __float22bfloat162_rn(make_float2(
                    v0 - __bfloat162float(hp.x), v1 - __bfloat162float(hp.y)));
                size_t off = ((size_t)((b << 3) + h) * Nn + n) * DHh + e;
                *(__nv_bfloat162*)(dh + off) = hp;
                *(__nv_bfloat162*)(dl + off) = lp;
            }
        }
    }
}

// ---------------------------------------------------------------------------
// K4: output projection on HMMA. out = att @ out_w + out_b
// ---------------------------------------------------------------------------
__global__ __launch_bounds__(256, 2) void k_out_mma(const float* __restrict__ bias,
                                                    float* __restrict__ out) {
    extern __shared__ char smg[];
    int tid = threadIdx.x;
    int n0 = blockIdx.x << 7, m0 = blockIdx.y << 7;

    float acc[4][4][4];
    #pragma unroll
    for (int mt = 0; mt < 4; mt++)
        #pragma unroll
        for (int nt = 0; nt < 4; nt++)
            acc[mt][nt][0] = acc[mt][nt][1] = acc[mt][nt][2] = acc[mt][nt][3] = 0.0f;

    hmma_mainloop(acc, smg, g_ath, g_atl, g_owth, g_owtl, m0, n0, tid);

    int lane = tid & 31, wid = tid >> 5;
    int wyBase = (wid >> 2) * 64, wxBase = (wid & 3) * 32;
    int g = lane >> 2, tig = lane & 3;

    #pragma unroll
    for (int mt = 0; mt < 4; mt++) {
        #pragma unroll
        for (int nt = 0; nt < 4; nt++) {
            int col = n0 + wxBase + (nt << 3) + (tig << 1);
            float2 bv = *(const float2*)(bias + col);
            #pragma unroll
            for (int half = 0; half < 2; half++) {
                int row = m0 + wyBase + (mt << 4) + g + (half << 3);
                *(float2*)(out + (size_t)row * Dd + col) =
                    make_float2(acc[mt][nt][half * 2] + bv.x,
                                acc[mt][nt][half * 2 + 1] + bv.y);
            }
        }
    }
}

// ---------------------------------------------------------------------------
// K2a: U = coords @ w1
// ---------------------------------------------------------------------------
__global__ __launch_bounds__(256) void k_proj(const float* __restrict__ coords,
                                              const float* __restrict__ w1) {
    int idx = blockIdx.x * 256 + threadIdx.x;
    int row = idx >> 5, m = idx & 31;
    float c0 = coords[row * 3 + 0];
    float c1 = coords[row * 3 + 1];
    float c2 = coords[row * 3 + 2];
    g_U[idx] = fmaf(c0, w1[m], fmaf(c1, w1[32 + m], c2 * w1[64 + m]));
}

// ---------------------------------------------------------------------------
// K2b: bias MLP (R10/R11 version)
// ---------------------------------------------------------------------------
__global__ __launch_bounds__(256) void k_bias(const float* __restrict__ b1,
                                              const float* __restrict__ w2,
                                              const float* __restrict__ b2) {
    __shared__ float  sUi[32 * 33];
    __shared__ float  sUj[32 * 33];
    __shared__ float2 sw2[HIDn * 4];
    __shared__ float2 sb2[4];

    int b  = blockIdx.z;
    int i0 = blockIdx.y << 5;
    int j0 = blockIdx.x << 5;
    int tid = threadIdx.x;

    {
        int r = tid >> 3, m4 = (tid & 7) << 2;
        float4 ui = *(const float4*)(g_U + ((size_t)(b << 10) + i0 + r) * HIDn + m4);
        float4 bb = *(const float4*)(b1 + m4);
        sUi[r * 33 + m4 + 0] = ui.x + bb.x;
        sUi[r * 33 + m4 + 1] = ui.y + bb.y;
        sUi[r * 33 + m4 + 2] = ui.z + bb.z;
        sUi[r * 33 + m4 + 3] = ui.w + bb.w;
        float4 uj = *(const float4*)(g_U + ((size_t)(b << 10) + j0 + r) * HIDn + m4);
        sUj[r * 33 + m4 + 0] = uj.x;
        sUj[r * 33 + m4 + 1] = uj.y;
        sUj[r * 33 + m4 + 2] = uj.z;
        sUj[r * 33 + m4 + 3] = uj.w;
    }
    if (tid < 128) {
        int m = tid >> 2, hp = tid & 3;
        sw2[m * 4 + hp] = *(const float2*)(w2 + m * Hh + (hp << 1));
    }
    if (tid < 4) sb2[tid] = *(const float2*)(b2 + (tid << 1));
    __syncthreads();

    #pragma unroll
    for (int q = 0; q < 4; q++) {
        int p = tid + (q << 8);
        int i = p >> 5, j = p & 31;
        const float* ui = sUi + i * 33;
        const float* uj = sUj + j * 33;
        float2 acc[4] = {sb2[0], sb2[1], sb2[2], sb2[3]};
        #pragma unroll
        for (int m = 0; m < HIDn; m++) {
            float hs = ui[m] - uj[m];
            float g  = 0.5f * hs * (1.0f + erff(hs * 0.70710678118654752f));
            float2 gg = make_float2(g, g);
            acc[0] = ffma2(gg, sw2[m * 4 + 0], acc[0]);
            acc[1] = ffma2(gg, sw2[m * 4 + 1], acc[1]);
            acc[2] = ffma2(gg, sw2[m * 4 + 2], acc[2]);
            acc[3] = ffma2(gg, sw2[m * 4 + 3], acc[3]);
        }
        size_t base = ((size_t)((b * Hh) << 10) + i0 + i) * Nn + j0 + j;
        float av[8] = {acc[0].x, acc[0].y, acc[1].x, acc[1].y,
                       acc[2].x, acc[2].y, acc[3].x, acc[3].y};
        #pragma unroll
        for (int h = 0; h < Hh; h++)
            g_bias[base + (size_t)h * (Nn * Nn)] = av[h];
    }
}

// ---------------------------------------------------------------------------
// K3: HMMA flash attention (R11 version, unchanged)
// ---------------------------------------------------------------------------
#define AOFF_KH 0
#define AOFF_KL 9216
#define AOFF_VH 18432
#define AOFF_VL 27648
#define AOFF_PH 36864
#define AOFF_PL 55296
#define AT_SMEM 73728

__global__ __launch_bounds__(256) void k_attn_mma(const unsigned char* __restrict__ mask) {
    extern __shared__ char smx[];
    uint32_t sb = smem_u32(smx);
    int tid = threadIdx.x, lane = tid & 31, w = tid >> 5;
    int g = lane >> 2, tig = lane & 3;
    int bh = blockIdx.y, i0 = blockIdx.x << 7;
    int b = bh >> 3, h = bh & 7;

    const __nv_bfloat16* Qh = g_qh + (size_t)bh * Nn * DHh;
    const __nv_bfloat16* Ql = g_ql + (size_t)bh * Nn * DHh;
    const __nv_bfloat16* Kh = g_kh + (size_t)bh * Nn * DHh;
    const __nv_bfloat16* Kl = g_kl + (size_t)bh * Nn * DHh;
    const __nv_bfloat16* Vh = g_vh + (size_t)bh * Nn * DHh;
    const __nv_bfloat16* Vl = g_vl + (size_t)bh * Nn * DHh;
    const unsigned char* mrow = mask + ((size_t)b << 10);
    int r0 = i0 + w * 16 + g;
    const float* br0 = g_bias + (size_t)bh * Nn * Nn + (size_t)r0 * Nn;
    const float* br1 = br0 + 8 * Nn;

    uint32_t qfh[4][4], qfl[4][4];
    #pragma unroll
    for (int pass = 0; pass < 2; pass++) {
        const __nv_bfloat16* src = pass ? Ql : Qh;
        int row = tid >> 1, off = (tid & 1) * 64;
        const uint4* s4 = (const uint4*)((const char*)(src + (size_t)(i0 + row) * DHh) + off);
        uint4* d4 = (uint4*)(smx + AOFF_PH + row * 144 + off);
        d4[0] = s4[0]; d4[1] = s4[1]; d4[2] = s4[2]; d4[3] = s4[3];
        __syncthreads();
        uint32_t base = sb + AOFF_PH + (uint32_t)((w * 16 + (lane & 15)) * 144 + ((lane >> 4) << 4));
        #pragma unroll
        for (int ks = 0; ks < 4; ks++)
            ldsm4(pass ? qfl[ks] : qfh[ks], base + ks * 32);
        __syncthreads();
    }

    float o[8][4];
    #pragma unroll
    for (int nt = 0; nt < 8; nt++)
        o[nt][0] = o[nt][1] = o[nt][2] = o[nt][3] = 0.0f;
    float m0 = -1e30f, m1 = -1e30f, l0 = 0.0f, l1 = 0.0f;

    for (int jt = 0; jt < 16; jt++) {
        int j0 = jt << 6;
        __syncthreads();
        {
            int row = tid >> 2, off = (tid & 3) * 32;
            size_t go = (size_t)(j0 + row) * DHh;
            const char* skh = (const char*)(Kh + go) + off;
            const char* skl = (const char*)(Kl + go) + off;
            const char* svh = (const char*)(Vh + go) + off;
            const char* svl = (const char*)(Vl + go) + off;
            char* d = smx + row * 144 + off;
            *(uint4*)(d + AOFF_KH)      = *(const uint4*)skh;
            *(uint4*)(d + AOFF_KH + 16) = *(const uint4*)(skh + 16);
            *(uint4*)(d + AOFF_KL)      = *(const uint4*)skl;
            *(uint4*)(d + AOFF_KL + 16) = *(const uint4*)(skl + 16);
            *(uint4*)(d + AOFF_VH)      = *(const uint4*)svh;
            *(uint4*)(d + AOFF_VH + 16) = *(const uint4*)(svh + 16);
            *(uint4*)(d + AOFF_VL)      = *(const uint4*)svl;
            *(uint4*)(d + AOFF_VL + 16) = *(const uint4*)(svl + 16);
        }

        float s[8][4];
        #pragma unroll
        for (int nt = 0; nt < 8; nt++) {
            int col = j0 + (nt << 3) + (tig << 1);
            float2 b0 = *(const float2*)(br0 + col);
            float2 b1 = *(const float2*)(br1 + col);
            s[nt][0] = b0.x; s[nt][1] = b0.y;
            s[nt][2] = b1.x; s[nt][3] = b1.y;
        }
        __syncthreads();

        #pragma unroll
        for (int ks = 0; ks < 4; ks++) {
            #pragma unroll
            for (int ng = 0; ng < 4; ng++) {
                int n  = (ng << 4) + (((lane >> 4) & 1) << 3) + (lane & 7);
                int kc = (ks << 4) + (((lane >> 3) & 1) << 3);
                uint32_t off = (uint32_t)(n * 144 + kc * 2);
                uint32_t th[4], tl[4];
                ldsm4(th, sb + AOFF_KH + off);
                ldsm4(tl, sb + AOFF_KL + off);
                uint32_t bh0[2] = {th[0], th[1]}, bh1[2] = {th[2], th[3]};
                uint32_t bl0[2] = {tl[0], tl[1]}, bl1[2] = {tl[2], tl[3]};
                mma16816(s[ng * 2 + 0], qfh[ks], bh0);
                mma16816(s[ng * 2 + 1], qfh[ks], bh1);
                mma16816(s[ng * 2 + 0], qfh[ks], bl0);
                mma16816(s[ng * 2 + 1], qfh[ks], bl1);
                mma16816(s[ng * 2 + 0], qfl[ks], bh0);
                mma16816(s[ng * 2 + 1], qfl[ks], bh1);
            }
        }

        #pragma unroll
        for (int nt = 0; nt < 8; nt++) {
            int col = j0 + (nt << 3) + (tig << 1);
            uchar2 mk = *(const uchar2*)(mrow + col);
            if (mk.x) { s[nt][0] = -1e30f; s[nt][2] = -1e30f; }
            if (mk.y) { s[nt][1] = -1e30f; s[nt][3] = -1e30f; }
        }

        float mx0 = -1e30f, mx1 = -1e30f;
        #pragma unroll
        for (int nt = 0; nt < 8; nt++) {
            mx0 = fmaxf(mx0, fmaxf(s[nt][0], s[nt][1]));
            mx1 = fmaxf(mx1, fmaxf(s[nt][2], s[nt][3]));
        }
        mx0 = fmaxf(mx0, __shfl_xor_sync(0xFFFFFFFFu, mx0, 1));
        mx0 = fmaxf(mx0, __shfl_xor_sync(0xFFFFFFFFu, mx0, 2));
        mx1 = fmaxf(mx1, __shfl_xor_sync(0xFFFFFFFFu, mx1, 1));
        mx1 = fmaxf(mx1, __shfl_xor_sync(0xFFFFFFFFu, mx1, 2));
        float mn0 = fmaxf(m0, mx0), f0 = __expf(m0 - mn0); m0 = mn0;
        float mn1 = fmaxf(m1, mx1), f1 = __expf(m1 - mn1); m1 = mn1;

        float ps0 = 0.0f, ps1 = 0.0f;
        int prow0 = (w * 16 + g) * 144;
        #pragma unroll
        for (int nt = 0; nt < 8; nt++) {
            float p00 = __expf(s[nt][0] - mn0);
            float p01 = __expf(s[nt][1] - mn0);
            float p10 = __expf(s[nt][2] - mn1);
            float p11 = __expf(s[nt][3] - mn1);
            ps0 += p00 + p01;
            ps1 += p10 + p11;
            int cb = ((nt << 3) + (tig << 1)) * 2;
            __nv_bfloat162 h0 = __float22bfloat162_rn(make_float2(p00, p01));
            __nv_bfloat162 l0p = __float22bfloat162_rn(make_float2(
                p00 - __bfloat162float(h0.x), p01 - __bfloat162float(h0.y)));
            __nv_bfloat162 h1 = __float22bfloat162_rn(make_float2(p10, p11));
            __nv_bfloat162 l1p = __float22bfloat162_rn(make_float2(
                p10 - __bfloat162float(h1.x), p11 - __bfloat162float(h1.y)));
            *(__nv_bfloat162*)(smx + AOFF_PH + prow0 + cb)         = h0;
            *(__nv_bfloat162*)(smx + AOFF_PL + prow0 + cb)         = l0p;
            *(__nv_bfloat162*)(smx + AOFF_PH + prow0 + 8*144 + cb) = h1;
            *(__nv_bfloat162*)(smx + AOFF_PL + prow0 + 8*144 + cb) = l1p;
        }
        l0 = l0 * f0 + ps0;
        l1 = l1 * f1 + ps1;
        #pragma unroll
        for (int nt = 0; nt < 8; nt++) {
            o[nt][0] *= f0; o[nt][1] *= f0;
            o[nt][2] *= f1; o[nt][3] *= f1;
        }
        __syncwarp();

        uint32_t abase = sb + (uint32_t)((w * 16 + (lane & 15)) * 144 + ((lane >> 4) << 4));
        #pragma unroll
        for (int ks = 0; ks < 4; ks++) {
            uint32_t ph[4], pl[4];
            ldsm4(ph, abase + AOFF_PH + ks * 32);
            ldsm4(pl, abase + AOFF_PL + ks * 32);
            #pragma unroll
            for (int eg = 0; eg < 4; eg++) {
                uint32_t voff = (uint32_t)(((ks << 4) + (lane & 15)) * 144 +
                                           (((eg << 4) + ((lane >> 4) << 3)) * 2));
                uint32_t th[4], tl[4];
                ldsm4t(th, sb + AOFF_VH + voff);
                ldsm4t(tl, sb + AOFF_VL + voff);
                uint32_t bh0[2] = {th[0], th[1]}, bh1[2] = {th[2], th[3]};
                uint32_t bl0[2] = {tl[0], tl[1]}, bl1[2] = {tl[2], tl[3]};
                mma16816(o[eg * 2 + 0], ph, bh0);
                mma16816(o[eg * 2 + 1], ph, bh1);
                mma16816(o[eg * 2 + 0], ph, bl0);
                mma16816(o[eg * 2 + 1], ph, bl1);
                mma16816(o[eg * 2 + 0], pl, bh0);
                mma16816(o[eg * 2 + 1], pl, bh1);
            }
        }
    }

    l0 += __shfl_xor_sync(0xFFFFFFFFu, l0, 1);
    l0 += __shfl_xor_sync(0xFFFFFFFFu, l0, 2);
    l1 += __shfl_xor_sync(0xFFFFFFFFu, l1, 1);
    l1 += __shfl_xor_sync(0xFFFFFFFFu, l1, 2);
    float inv0 = __frcp_rn(l0), inv1 = __frcp_rn(l1);
    #pragma unroll
    for (int nt = 0; nt < 8; nt++) {
        int e = (nt << 3) + (tig << 1);
        #pragma unroll
        for (int half = 0; half < 2; half++) {
            float inv = half ? inv1 : inv0;
            int row = r0 + (half << 3);
            float v0 = o[nt][half * 2]     * inv;
            float v1 = o[nt][half * 2 + 1] * inv;
            __nv_bfloat162 hp = __float22bfloat162_rn(make_float2(v0, v1));
            __nv_bfloat162 lp = __float22bfloat162_rn(make_float2(
                v0 - __bfloat162float(hp.x), v1 - __bfloat162float(hp.y)));
            size_t off = ((size_t)(b << 10) + row) * Dd + h * DHh + e;
            *(__nv_bfloat162*)(g_ath + off) = hp;
            *(__nv_bfloat162*)(g_atl + off) = lp;
        }
    }
}

// ---------------------------------------------------------------------------
// Launch: fork bias chain onto a second stream, join before attention.
// Streams/events created once on the (uncaptured) correctness call; the
// event fork/join pattern is capturable into the CUDA graph.
// ---------------------------------------------------------------------------
extern "C" void kernel_launch(void* const* d_in, const int* in_sizes, int n_in,
                              void* d_out, int out_size) {
    const float*         x      = (const float*)d_in[0];
    const float*         coords = (const float*)d_in[1];
    const unsigned char* mask   = (const unsigned char*)d_in[2];
    const float*         qkv_w  = (const float*)d_in[3];
    const float*         out_w  = (const float*)d_in[4];
    const float*         out_b  = (const float*)d_in[5];
    const float*         w1     = (const float*)d_in[6];
    const float*         b1     = (const float*)d_in[7];
    const float*         w2     = (const float*)d_in[8];
    const float*         b2     = (const float*)d_in[9];
    float*               out    = (float*)d_out;

    static cudaStream_t s2 = nullptr;
    static cudaEvent_t evF = nullptr, evJ = nullptr;
    if (!s2) {
        cudaStreamCreateWithFlags(&s2, cudaStreamNonBlocking);
        cudaEventCreateWithFlags(&evF, cudaEventDisableTiming);
        cudaEventCreateWithFlags(&evJ, cudaEventDisableTiming);
        cudaFuncSetAttribute(k_attn_mma, cudaFuncAttributeMaxDynamicSharedMemorySize, AT_SMEM);
        cudaFuncSetAttribute(k_qkv_mma,  cudaFuncAttributeMaxDynamicSharedMemorySize, GEMM_SMEM);
        cudaFuncSetAttribute(k_out_mma,  cudaFuncAttributeMaxDynamicSharedMemorySize, GEMM_SMEM);
    }

    // fork
    cudaEventRecord(evF, 0);
    cudaStreamWaitEvent(s2, evF, 0);

    // stream s2: bias chain + out_w split (independent of QKV chain)
    k_proj  <<<512, 256, 0, s2>>>(coords, w1);
    k_bias  <<<dim3(32, 32, Bb), 256, 0, s2>>>(b1, w2, b2);
    k_splitT<<<dim3(16, 16), dim3(32, 32), 0, s2>>>(out_w, Dd, Dd, 1);

    // default stream: QKV chain
    k_split_x<<<2048, 256>>>((const float4*)x);
    k_splitT <<<dim3(48, 16), dim3(32, 32)>>>(qkv_w, Dd, 3 * Dd, 0);
    k_qkv_mma<<<dim3(12, 32), 256, GEMM_SMEM>>>();

    // join
    cudaEventRecord(evJ, s2);
    cudaStreamWaitEvent(0, evJ, 0);

    k_attn_mma<<<dim3(8, 32), 256, AT_SMEM>>>(mask);
    k_out_mma <<<dim3(4, 32), 256, GEMM_SMEM>>>(out_b, out);
}

// round 13
// speedup vs baseline: 1.5719x; 1.2583x over previous
#include <cuda_runtime.h>
#include <cuda_bf16.h>
#include <math.h>
#include <stdint.h>

#define Bb   4
#define Nn   1024
#define Dd   512
#define Hh   8
#define DHh  64
#define HIDn 32

// ---------------------------------------------------------------------------
// Static scratch (allocation-free per harness rules)
// ---------------------------------------------------------------------------
__device__ float g_bias[(size_t)Bb*Hh*Nn*Nn];     // [B,H,N,N] additive bias
__device__ float g_U[Bb*Nn*HIDn];                 // coords @ w1  [B,N,32]

// bf16 hi/lo operands
__device__ __nv_bfloat16 g_xh[4096*512],  g_xl[4096*512];    // x          [M,K]
__device__ __nv_bfloat16 g_wth[1536*512], g_wtl[1536*512];   // qkv_w^T    [N,K]
__device__ __nv_bfloat16 g_ath[4096*512], g_atl[4096*512];   // att        [M,K]
__device__ __nv_bfloat16 g_owth[512*512], g_owtl[512*512];   // out_w^T    [N,K]
__device__ __nv_bfloat16 g_qh[Bb*Hh*Nn*DHh], g_ql[Bb*Hh*Nn*DHh];  // q (x0.125)
__device__ __nv_bfloat16 g_kh[Bb*Hh*Nn*DHh], g_kl[Bb*Hh*Nn*DHh];
__device__ __nv_bfloat16 g_vh[Bb*Hh*Nn*DHh], g_vl[Bb*Hh*Nn*DHh];

// ---------------------------------------------------------------------------
// Packed fp32x2 FMA (k_bias only — operands pack cleanly there)
// ---------------------------------------------------------------------------
__device__ __forceinline__ float2 ffma2(float2 a, float2 b, float2 c) {
    float2 d;
    asm("fma.rn.f32x2 %0, %1, %2, %3;"
        : "=l"(*(unsigned long long*)&d)
        : "l"(*(unsigned long long*)&a),
          "l"(*(unsigned long long*)&b),
          "l"(*(unsigned long long*)&c));
    return d;
}

// Branch-free exact-GELU: 0.5x(1+erf(x/sqrt2)) with A&S 7.1.26 5-term erf
// (|err| <= 1.5e-7). rcp.approx + __expf run on MUFU, relieving the FMA pipe.
__device__ __forceinline__ float gelu_exact(float x) {
    float z = 0.70710678118654752f * fabsf(x);
    float d = fmaf(0.3275911f, z, 1.0f);
    float t;
    asm("rcp.approx.f32 %0, %1;" : "=f"(t) : "f"(d));
    float p = fmaf(1.061405429f, t, -1.453152027f);
    p = fmaf(p, t, 1.421413741f);
    p = fmaf(p, t, -0.284496736f);
    p = fmaf(p, t, 0.254829592f);
    p *= t;
    float e = __expf(-z * z);
    float erfv = fmaf(-p, e, 1.0f);
    erfv = copysignf(erfv, x);
    float hx = 0.5f * x;
    return fmaf(hx, erfv, hx);
}

// ---------------------------------------------------------------------------
// mma.sync / ldmatrix / cp.async helpers (baseline PTX, OK on plain sm_103)
// ---------------------------------------------------------------------------
__device__ __forceinline__ uint32_t smem_u32(const void* p) {
    uint32_t a;
    asm("{ .reg .u64 t; cvta.to.shared.u64 t, %1; cvt.u32.u64 %0, t; }" : "=r"(a) : "l"(p));
    return a;
}
__device__ __forceinline__ void ldsm4(uint32_t r[4], uint32_t addr) {
    asm volatile("ldmatrix.sync.aligned.m8n8.x4.shared.b16 {%0,%1,%2,%3}, [%4];"
        : "=r"(r[0]), "=r"(r[1]), "=r"(r[2]), "=r"(r[3]) : "r"(addr));
}
__device__ __forceinline__ void ldsm4t(uint32_t r[4], uint32_t addr) {
    asm volatile("ldmatrix.sync.aligned.m8n8.x4.trans.shared.b16 {%0,%1,%2,%3}, [%4];"
        : "=r"(r[0]), "=r"(r[1]), "=r"(r[2]), "=r"(r[3]) : "r"(addr));
}
__device__ __forceinline__ void mma16816(float c[4], const uint32_t a[4], const uint32_t b[2]) {
    asm volatile("mma.sync.aligned.m16n8k16.row.col.f32.bf16.bf16.f32 "
        "{%0,%1,%2,%3}, {%4,%5,%6,%7}, {%8,%9}, {%0,%1,%2,%3};"
        : "+f"(c[0]), "+f"(c[1]), "+f"(c[2]), "+f"(c[3])
        : "r"(a[0]), "r"(a[1]), "r"(a[2]), "r"(a[3]), "r"(b[0]), "r"(b[1]));
}
__device__ __forceinline__ void cp16(uint32_t dst, const void* src) {
    asm volatile("cp.async.ca.shared.global [%0], [%1], 16;" :: "r"(dst), "l"(src));
}
#define CP_COMMIT() asm volatile("cp.async.commit_group;" ::: "memory")
#define CP_WAIT(n)  asm volatile("cp.async.wait_group %0;" :: "n"(n) : "memory")

#define TP 40   // GEMM smem tile pitch (bf16)

// ---------------------------------------------------------------------------
// hi/lo bf16 split kernels (input x + weight transposes)
// ---------------------------------------------------------------------------
__global__ __launch_bounds__(256) void k_split_x(const float4* __restrict__ src) {
    size_t i = (size_t)blockIdx.x * 256 + threadIdx.x;
    float4 v = src[i];
    float a[4] = {v.x, v.y, v.z, v.w};
    __nv_bfloat16 h[4], l[4];
    #pragma unroll
    for (int j = 0; j < 4; j++) {
        h[j] = __float2bfloat16_rn(a[j]);
        l[j] = __float2bfloat16_rn(a[j] - __bfloat162float(h[j]));
    }
    ((__nv_bfloat162*)g_xh)[2*i]   = __halves2bfloat162(h[0], h[1]);
    ((__nv_bfloat162*)g_xh)[2*i+1] = __halves2bfloat162(h[2], h[3]);
    ((__nv_bfloat162*)g_xl)[2*i]   = __halves2bfloat162(l[0], l[1]);
    ((__nv_bfloat162*)g_xl)[2*i+1] = __halves2bfloat162(l[2], l[3]);
}

__global__ void k_splitT(const float* __restrict__ src, int K, int N, int which) {
    __shared__ float ts[32][33];
    int kk = blockIdx.y * 32 + threadIdx.y;
    int nn = blockIdx.x * 32 + threadIdx.x;
    ts[threadIdx.y][threadIdx.x] = src[(size_t)kk * N + nn];
    __syncthreads();
    int on = blockIdx.x * 32 + threadIdx.y;
    int ok = blockIdx.y * 32 + threadIdx.x;
    float v = ts[threadIdx.x][threadIdx.y];
    __nv_bfloat16 h = __float2bfloat16_rn(v);
    __nv_bfloat16 l = __float2bfloat16_rn(v - __bfloat162float(h));
    __nv_bfloat16* hd = which ? g_owth : g_wth;
    __nv_bfloat16* ld = which ? g_owtl : g_wtl;
    hd[(size_t)on * K + ok] = h;
    ld[(size_t)on * K + ok] = l;
}

// ---------------------------------------------------------------------------
// HMMA bf16x3 GEMM mainloop — cp.async double-buffered (R12, unchanged)
// ---------------------------------------------------------------------------
#define TILE_B   (128 * TP * 2)
#define BUF_B    (4 * TILE_B)
#define GEMM_SMEM (2 * BUF_B)

__device__ __forceinline__ void cp_tile(uint32_t dst, const __nv_bfloat16* __restrict__ src,
                                        int row0, int k0, int tid) {
    #pragma unroll
    for (int i = 0; i < 2; i++) {
        int idx = tid + (i << 8);
        int rr = idx >> 2, sg = idx & 3;
        cp16(dst + (uint32_t)((rr * TP) * 2 + sg * 16),
             (const char*)src + ((size_t)(row0 + rr) * 512 + k0) * 2 + sg * 16);
    }
}

__device__ __forceinline__ void issue_chunk(uint32_t sb, int buf,
    const __nv_bfloat16* Ah, const __nv_bfloat16* Al,
    const __nv_bfloat16* Bh, const __nv_bfloat16* Bl,
    int m0, int n0, int k0, int tid)
{
    uint32_t b = sb + buf * BUF_B;
    cp_tile(b + 0 * TILE_B, Ah, m0, k0, tid);
    cp_tile(b + 1 * TILE_B, Al, m0, k0, tid);
    cp_tile(b + 2 * TILE_B, Bh, n0, k0, tid);
    cp_tile(b + 3 * TILE_B, Bl, n0, k0, tid);
    CP_COMMIT();
}

__device__ __forceinline__ void mma_all(float acc[4][4][4],
                                        const uint32_t a[4][4],
                                        const uint32_t b[4][2]) {
    #pragma unroll
    for (int mt = 0; mt < 4; mt++)
        #pragma unroll
        for (int nt = 0; nt < 4; nt++)
            mma16816(acc[mt][nt], a[mt], b[nt]);
}

__device__ __forceinline__ void load_afrag(uint32_t a[4][4], uint32_t base_u32,
                                           int wyBase, int kb, int lane) {
    int r  = wyBase + (lane & 15);
    int kc = (kb << 4) + ((lane >> 4) << 3);
    uint32_t addr = base_u32 + (uint32_t)(r * TP + kc) * 2;
    #pragma unroll
    for (int mt = 0; mt < 4; mt++)
        ldsm4(a[mt], addr + mt * (16 * TP * 2));
}

__device__ __forceinline__ void load_bfrag(uint32_t b[4][2], uint32_t base_u32,
                                           int wxBase, int kb, int lane) {
    int n  = wxBase + (((lane >> 4) & 1) << 3) + (lane & 7);
    int kc = (kb << 4) + (((lane >> 3) & 1) << 3);
    uint32_t addr = base_u32 + (uint32_t)(n * TP + kc) * 2;
    #pragma unroll
    for (int np = 0; np < 2; np++) {
        uint32_t t4[4];
        ldsm4(t4, addr + np * (16 * TP * 2));
        b[np * 2 + 0][0] = t4[0]; b[np * 2 + 0][1] = t4[1];
        b[np * 2 + 1][0] = t4[2]; b[np * 2 + 1][1] = t4[3];
    }
}

__device__ __forceinline__ void hmma_mainloop(
    float acc[4][4][4], char* smem,
    const __nv_bfloat16* Ah, const __nv_bfloat16* Al,
    const __nv_bfloat16* Bh, const __nv_bfloat16* Bl,
    int m0, int n0, int tid)
{
    int lane = tid & 31, wid = tid >> 5;
    int wyBase = (wid >> 2) * 64, wxBase = (wid & 3) * 32;
    uint32_t sb = smem_u32(smem);

    issue_chunk(sb, 0, Ah, Al, Bh, Bl, m0, n0, 0, tid);
    #pragma unroll 1
    for (int c = 0; c < 16; c++) {
        if (c < 15) {
            issue_chunk(sb, (c + 1) & 1, Ah, Al, Bh, Bl, m0, n0, (c + 1) * 32, tid);
            CP_WAIT(1);
        } else {
            CP_WAIT(0);
        }
        __syncthreads();
        uint32_t base = sb + (c & 1) * BUF_B;
        uint32_t uAh = base, uAl = base + TILE_B;
        uint32_t uBh = base + 2 * TILE_B, uBl = base + 3 * TILE_B;
        #pragma unroll
        for (int kb = 0; kb < 2; kb++) {
            uint32_t a[4][4], b[4][2];
            load_afrag(a, uAh, wyBase, kb, lane);
            load_bfrag(b, uBl, wxBase, kb, lane);
            mma_all(acc, a, b);
            load_bfrag(b, uBh, wxBase, kb, lane);
            mma_all(acc, a, b);
            load_afrag(a, uAl, wyBase, kb, lane);
            mma_all(acc, a, b);
        }
        __syncthreads();
    }
}

// ---------------------------------------------------------------------------
// K1: QKV projection on HMMA; epilogue writes q/k/v as bf16 hi/lo (q x0.125).
// ---------------------------------------------------------------------------
__global__ __launch_bounds__(256, 2) void k_qkv_mma() {
    extern __shared__ char smg[];
    int tid = threadIdx.x;
    int n0 = blockIdx.x << 7, m0 = blockIdx.y << 7;

    float acc[4][4][4];
    #pragma unroll
    for (int mt = 0; mt < 4; mt++)
        #pragma unroll
        for (int nt = 0; nt < 4; nt++)
            acc[mt][nt][0] = acc[mt][nt][1] = acc[mt][nt][2] = acc[mt][nt][3] = 0.0f;

    hmma_mainloop(acc, smg, g_xh, g_xl, g_wth, g_wtl, m0, n0, tid);

    int lane = tid & 31, wid = tid >> 5;
    int wyBase = (wid >> 2) * 64, wxBase = (wid & 3) * 32;
    int g = lane >> 2, tig = lane & 3;

    int sec = n0 >> 9;
    float s = (sec == 0) ? 0.125f : 1.0f;
    __nv_bfloat16* dh = (sec == 0) ? g_qh : (sec == 1) ? g_kh : g_vh;
    __nv_bfloat16* dl = (sec == 0) ? g_ql : (sec == 1) ? g_kl : g_vl;

    #pragma unroll
    for (int mt = 0; mt < 4; mt++) {
        #pragma unroll
        for (int nt = 0; nt < 4; nt++) {
            int col = n0 + wxBase + (nt << 3) + (tig << 1);
            int h = (col & 511) >> 6, e = col & 63;
            #pragma unroll
            for (int half = 0; half < 2; half++) {
                int row = m0 + wyBase + (mt << 4) + g + (half << 3);
                int b = row >> 10, n = row & 1023;
                float v0 = acc[mt][nt][half * 2]     * s;
                float v1 = acc[mt][nt][half * 2 + 1] * s;
                __nv_bfloat162 hp = __float22bfloat162_rn(make_float2(v0, v1));
                __nv_bfloat162 lp = __float22bfloat162_rn(make_float2(
                    v0 - __bfloat162float(hp.x), v1 - __bfloat162float(hp.y)));
                size_t off = ((size_t)((b << 3) + h) * Nn + n) * DHh + e;
                *(__nv_bfloat162*)(dh + off) = hp;
                *(__nv_bfloat162*)(dl + off) = lp;
            }
        }
    }
}

// ---------------------------------------------------------------------------
// K4: output projection on HMMA. out = att @ out_w + out_b
// ---------------------------------------------------------------------------
__global__ __launch_bounds__(256, 2) void k_out_mma(const float* __restrict__ bias,
                                                    float* __restrict__ out) {
    extern __shared__ char smg[];
    int tid = threadIdx.x;
    int n0 = blockIdx.x << 7, m0 = blockIdx.y << 7;

    float acc[4][4][4];
    #pragma unroll
    for (int mt = 0; mt < 4; mt++)
        #pragma unroll
        for (int nt = 0; nt < 4; nt++)
            acc[mt][nt][0] = acc[mt][nt][1] = acc[mt][nt][2] = acc[mt][nt][3] = 0.0f;

    hmma_mainloop(acc, smg, g_ath, g_atl, g_owth, g_owtl, m0, n0, tid);

    int lane = tid & 31, wid = tid >> 5;
    int wyBase = (wid >> 2) * 64, wxBase = (wid & 3) * 32;
    int g = lane >> 2, tig = lane & 3;

    #pragma unroll
    for (int mt = 0; mt < 4; mt++) {
        #pragma unroll
        for (int nt = 0; nt < 4; nt++) {
            int col = n0 + wxBase + (nt << 3) + (tig << 1);
            float2 bv = *(const float2*)(bias + col);
            #pragma unroll
            for (int half = 0; half < 2; half++) {
                int row = m0 + wyBase + (mt << 4) + g + (half << 3);
                *(float2*)(out + (size_t)row * Dd + col) =
                    make_float2(acc[mt][nt][half * 2] + bv.x,
                                acc[mt][nt][half * 2 + 1] + bv.y);
            }
        }
    }
}

// ---------------------------------------------------------------------------
// K2a: U = coords @ w1
// ---------------------------------------------------------------------------
__global__ __launch_bounds__(256) void k_proj(const float* __restrict__ coords,
                                              const float* __restrict__ w1) {
    int idx = blockIdx.x * 256 + threadIdx.x;
    int row = idx >> 5, m = idx & 31;
    float c0 = coords[row * 3 + 0];
    float c1 = coords[row * 3 + 1];
    float c2 = coords[row * 3 + 2];
    g_U[idx] = fmaf(c0, w1[m], fmaf(c1, w1[32 + m], c2 * w1[64 + m]));
}

// ---------------------------------------------------------------------------
// K2b: bias MLP v3. Per thread the 4 pairs p = tid + q*256 share j (p&31) and
// step i by 8 — hoist m outer, share uj[m] and all sw2 broadcasts across q.
// ---------------------------------------------------------------------------
__global__ __launch_bounds__(256) void k_bias(const float* __restrict__ b1,
                                              const float* __restrict__ w2,
                                              const float* __restrict__ b2) {
    __shared__ float  sUi[32 * 33];
    __shared__ float  sUj[32 * 33];
    __shared__ float2 sw2[HIDn * 4];
    __shared__ float2 sb2v[4];

    int b  = blockIdx.z;
    int i0 = blockIdx.y << 5;
    int j0 = blockIdx.x << 5;
    int tid = threadIdx.x;

    {
        int r = tid >> 3, m4 = (tid & 7) << 2;
        float4 ui = *(const float4*)(g_U + ((size_t)(b << 10) + i0 + r) * HIDn + m4);
        float4 bb = *(const float4*)(b1 + m4);
        sUi[r * 33 + m4 + 0] = ui.x + bb.x;
        sUi[r * 33 + m4 + 1] = ui.y + bb.y;
        sUi[r * 33 + m4 + 2] = ui.z + bb.z;
        sUi[r * 33 + m4 + 3] = ui.w + bb.w;
        float4 uj = *(const float4*)(g_U + ((size_t)(b << 10) + j0 + r) * HIDn + m4);
        sUj[r * 33 + m4 + 0] = uj.x;
        sUj[r * 33 + m4 + 1] = uj.y;
        sUj[r * 33 + m4 + 2] = uj.z;
        sUj[r * 33 + m4 + 3] = uj.w;
    }
    if (tid < 128) {
        int m = tid >> 2, hp = tid & 3;
        sw2[m * 4 + hp] = *(const float2*)(w2 + m * Hh + (hp << 1));
    }
    if (tid < 4) sb2v[tid] = *(const float2*)(b2 + (tid << 1));
    __syncthreads();

    int j  = tid & 31;
    int ib = tid >> 5;                       // i = ib + 8q
    const float* uj = sUj + j * 33;
    const float* ui = sUi + ib * 33;

    float2 acc[4][4];
    #pragma unroll
    for (int q = 0; q < 4; q++) {
        acc[q][0] = sb2v[0]; acc[q][1] = sb2v[1];
        acc[q][2] = sb2v[2]; acc[q][3] = sb2v[3];
    }

    #pragma unroll 8
    for (int m = 0; m < HIDn; m++) {
        float ujm = uj[m];
        float2 w0 = sw2[m * 4 + 0], w1v = sw2[m * 4 + 1];
        float2 w2v = sw2[m * 4 + 2], w3v = sw2[m * 4 + 3];
        #pragma unroll
        for (int q = 0; q < 4; q++) {
            float g = gelu_exact(ui[q * 264 + m] - ujm);   // 264 = 8*33
            float2 gg = make_float2(g, g);
            acc[q][0] = ffma2(gg, w0,  acc[q][0]);
            acc[q][1] = ffma2(gg, w1v, acc[q][1]);
            acc[q][2] = ffma2(gg, w2v, acc[q][2]);
            acc[q][3] = ffma2(gg, w3v, acc[q][3]);
        }
    }

    #pragma unroll
    for (int q = 0; q < 4; q++) {
        int i = ib + (q << 3);
        size_t base = ((size_t)((b * Hh) << 10) + i0 + i) * Nn + j0 + j;
        float av[8] = {acc[q][0].x, acc[q][0].y, acc[q][1].x, acc[q][1].y,
                       acc[q][2].x, acc[q][2].y, acc[q][3].x, acc[q][3].y};
        #pragma unroll
        for (int h = 0; h < Hh; h++)
            g_bias[base + (size_t)h * (Nn * Nn)] = av[h];
    }
}

// ---------------------------------------------------------------------------
// K3: HMMA flash attention with cp.async double-buffered K/V tiles.
// smem: 2 x [KH,KL,VH,VL] (64x144B each) + PH,PL (128x144B) = 110592 B.
// ---------------------------------------------------------------------------
#define KVBUF   36864
#define AOFF_PH 73728
#define AOFF_PL 92160
#define AT_SMEM 110592

__device__ __forceinline__ void attn_issue_kv(uint32_t sb, char* smx, int buf,
    const __nv_bfloat16* Kh, const __nv_bfloat16* Kl,
    const __nv_bfloat16* Vh, const __nv_bfloat16* Vl, int j0, int tid)
{
    int row = tid >> 2, off = (tid & 3) * 32;
    size_t go = (size_t)(j0 + row) * DHh;
    uint32_t d = sb + (uint32_t)(buf * KVBUF + row * 144 + off);
    cp16(d + 0,          (const char*)(Kh + go) + off);
    cp16(d + 16,         (const char*)(Kh + go) + off + 16);
    cp16(d + 9216,       (const char*)(Kl + go) + off);
    cp16(d + 9216 + 16,  (const char*)(Kl + go) + off + 16);
    cp16(d + 18432,      (const char*)(Vh + go) + off);
    cp16(d + 18432 + 16, (const char*)(Vh + go) + off + 16);
    cp16(d + 27648,      (const char*)(Vl + go) + off);
    cp16(d + 27648 + 16, (const char*)(Vl + go) + off + 16);
    CP_COMMIT();
}

__global__ __launch_bounds__(256) void k_attn_mma(const unsigned char* __restrict__ mask) {
    extern __shared__ char smx[];
    uint32_t sb = smem_u32(smx);
    int tid = threadIdx.x, lane = tid & 31, w = tid >> 5;
    int g = lane >> 2, tig = lane & 3;
    int bh = blockIdx.y, i0 = blockIdx.x << 7;
    int b = bh >> 3, h = bh & 7;

    const __nv_bfloat16* Qh = g_qh + (size_t)bh * Nn * DHh;
    const __nv_bfloat16* Ql = g_ql + (size_t)bh * Nn * DHh;
    const __nv_bfloat16* Kh = g_kh + (size_t)bh * Nn * DHh;
    const __nv_bfloat16* Kl = g_kl + (size_t)bh * Nn * DHh;
    const __nv_bfloat16* Vh = g_vh + (size_t)bh * Nn * DHh;
    const __nv_bfloat16* Vl = g_vl + (size_t)bh * Nn * DHh;
    const unsigned char* mrow = mask + ((size_t)b << 10);
    int r0 = i0 + w * 16 + g;
    const float* br0 = g_bias + (size_t)bh * Nn * Nn + (size_t)r0 * Nn;
    const float* br1 = br0 + 8 * Nn;

    // prefetch first K/V tile while staging Q
    attn_issue_kv(sb, smx, 0, Kh, Kl, Vh, Vl, 0, tid);

    // stage Q fragments into registers (hi then lo, via P buffer)
    uint32_t qfh[4][4], qfl[4][4];
    #pragma unroll
    for (int pass = 0; pass < 2; pass++) {
        const __nv_bfloat16* src = pass ? Ql : Qh;
        int row = tid >> 1, off = (tid & 1) * 64;
        const uint4* s4 = (const uint4*)((const char*)(src + (size_t)(i0 + row) * DHh) + off);
        uint4* d4 = (uint4*)(smx + AOFF_PH + row * 144 + off);
        d4[0] = s4[0]; d4[1] = s4[1]; d4[2] = s4[2]; d4[3] = s4[3];
        __syncthreads();
        uint32_t base = sb + AOFF_PH + (uint32_t)((w * 16 + (lane & 15)) * 144 + ((lane >> 4) << 4));
        #pragma unroll
        for (int ks = 0; ks < 4; ks++)
            ldsm4(pass ? qfl[ks] : qfh[ks], base + ks * 32);
        __syncthreads();
    }

    float o[8][4];
    #pragma unroll
    for (int nt = 0; nt < 8; nt++)
        o[nt][0] = o[nt][1] = o[nt][2] = o[nt][3] = 0.0f;
    float m0 = -1e30f, m1 = -1e30f, l0 = 0.0f, l1 = 0.0f;

    #pragma unroll 1
    for (int jt = 0; jt < 16; jt++) {
        int j0 = jt << 6;
        CP_WAIT(0);
        __syncthreads();                       // KV ready; prior PV reads done
        if (jt < 15)
            attn_issue_kv(sb, smx, (jt + 1) & 1, Kh, Kl, Vh, Vl, (jt + 1) << 6, tid);

        uint32_t kvb = sb + (uint32_t)((jt & 1) * KVBUF);

        // init S accumulators with bias (MMA accumulates on top)
        float s[8][4];
        #pragma unroll
        for (int nt = 0; nt < 8; nt++) {
            int col = j0 + (nt << 3) + (tig << 1);
            float2 b0 = *(const float2*)(br0 + col);
            float2 b1 = *(const float2*)(br1 + col);
            s[nt][0] = b0.x; s[nt][1] = b0.y;
            s[nt][2] = b1.x; s[nt][3] = b1.y;
        }

        // S += Q K^T (bf16x3)
        #pragma unroll
        for (int ks = 0; ks < 4; ks++) {
            #pragma unroll
            for (int ng = 0; ng < 4; ng++) {
                int n  = (ng << 4) + (((lane >> 4) & 1) << 3) + (lane & 7);
                int kc = (ks << 4) + (((lane >> 3) & 1) << 3);
                uint32_t off = (uint32_t)(n * 144 + kc * 2);
                uint32_t th[4], tl[4];
                ldsm4(th, kvb + off);              // KH
                ldsm4(tl, kvb + 9216 + off);       // KL
                uint32_t bh0[2] = {th[0], th[1]}, bh1[2] = {th[2], th[3]};
                uint32_t bl0[2] = {tl[0], tl[1]}, bl1[2] = {tl[2], tl[3]};
                mma16816(s[ng * 2 + 0], qfh[ks], bh0);
                mma16816(s[ng * 2 + 1], qfh[ks], bh1);
                mma16816(s[ng * 2 + 0], qfh[ks], bl0);
                mma16816(s[ng * 2 + 1], qfh[ks], bl1);
                mma16816(s[ng * 2 + 0], qfl[ks], bh0);
                mma16816(s[ng * 2 + 1], qfl[ks], bh1);
            }
        }

        // mask
        #pragma unroll
        for (int nt = 0; nt < 8; nt++) {
            int col = j0 + (nt << 3) + (tig << 1);
            uchar2 mk = *(const uchar2*)(mrow + col);
            if (mk.x) { s[nt][0] = -1e30f; s[nt][2] = -1e30f; }
            if (mk.y) { s[nt][1] = -1e30f; s[nt][3] = -1e30f; }
        }

        // online softmax (warp-local rows; quad reduction)
        float mx0 = -1e30f, mx1 = -1e30f;
        #pragma unroll
        for (int nt = 0; nt < 8; nt++) {
            mx0 = fmaxf(mx0, fmaxf(s[nt][0], s[nt][1]));
            mx1 = fmaxf(mx1, fmaxf(s[nt][2], s[nt][3]));
        }
        mx0 = fmaxf(mx0, __shfl_xor_sync(0xFFFFFFFFu, mx0, 1));
        mx0 = fmaxf(mx0, __shfl_xor_sync(0xFFFFFFFFu, mx0, 2));
        mx1 = fmaxf(mx1, __shfl_xor_sync(0xFFFFFFFFu, mx1, 1));
        mx1 = fmaxf(mx1, __shfl_xor_sync(0xFFFFFFFFu, mx1, 2));
        float mn0 = fmaxf(m0, mx0), f0 = __expf(m0 - mn0); m0 = mn0;
        float mn1 = fmaxf(m1, mx1), f1 = __expf(m1 - mn1); m1 = mn1;

        float ps0 = 0.0f, ps1 = 0.0f;
        int prow0 = (w * 16 + g) * 144;
        #pragma unroll
        for (int nt = 0; nt < 8; nt++) {
            float p00 = __expf(s[nt][0] - mn0);
            float p01 = __expf(s[nt][1] - mn0);
            float p10 = __expf(s[nt][2] - mn1);
            float p11 = __expf(s[nt][3] - mn1);
            ps0 += p00 + p01;
            ps1 += p10 + p11;
            int cb = ((nt << 3) + (tig << 1)) * 2;
            __nv_bfloat162 h0 = __float22bfloat162_rn(make_float2(p00, p01));
            __nv_bfloat162 l0p = __float22bfloat162_rn(make_float2(
                p00 - __bfloat162float(h0.x), p01 - __bfloat162float(h0.y)));
            __nv_bfloat162 h1 = __float22bfloat162_rn(make_float2(p10, p11));
            __nv_bfloat162 l1p = __float22bfloat162_rn(make_float2(
                p10 - __bfloat162float(h1.x), p11 - __bfloat162float(h1.y)));
            *(__nv_bfloat162*)(smx + AOFF_PH + prow0 + cb)         = h0;
            *(__nv_bfloat162*)(smx + AOFF_PL + prow0 + cb)         = l0p;
            *(__nv_bfloat162*)(smx + AOFF_PH + prow0 + 8*144 + cb) = h1;
            *(__nv_bfloat162*)(smx + AOFF_PL + prow0 + 8*144 + cb) = l1p;
        }
        l0 = l0 * f0 + ps0;
        l1 = l1 * f1 + ps1;
        #pragma unroll
        for (int nt = 0; nt < 8; nt++) {
            o[nt][0] *= f0; o[nt][1] *= f0;
            o[nt][2] *= f1; o[nt][3] *= f1;
        }
        __syncwarp();                    // P rows are warp-private

        // O += P V (bf16x3); V B-frags via ldmatrix.trans from [j][e]
        uint32_t abase = sb + (uint32_t)((w * 16 + (lane & 15)) * 144 + ((lane >> 4) << 4));
        #pragma unroll
        for (int ks = 0; ks < 4; ks++) {
            uint32_t ph[4], pl[4];
            ldsm4(ph, abase + AOFF_PH + ks * 32);
            ldsm4(pl, abase + AOFF_PL + ks * 32);
            #pragma unroll
            for (int eg = 0; eg < 4; eg++) {
                uint32_t voff = (uint32_t)(((ks << 4) + (lane & 15)) * 144 +
                                           (((eg << 4) + ((lane >> 4) << 3)) * 2));
                uint32_t th[4], tl[4];
                ldsm4t(th, kvb + 18432 + voff);    // VH
                ldsm4t(tl, kvb + 27648 + voff);    // VL
                uint32_t bh0[2] = {th[0], th[1]}, bh1[2] = {th[2], th[3]};
                uint32_t bl0[2] = {tl[0], tl[1]}, bl1[2] = {tl[2], tl[3]};
                mma16816(o[eg * 2 + 0], ph, bh0);
                mma16816(o[eg * 2 + 1], ph, bh1);
                mma16816(o[eg * 2 + 0], ph, bl0);
                mma16816(o[eg * 2 + 1], ph, bl1);
                mma16816(o[eg * 2 + 0], pl, bh0);
                mma16816(o[eg * 2 + 1], pl, bh1);
            }
        }
    }

    l0 += __shfl_xor_sync(0xFFFFFFFFu, l0, 1);
    l0 += __shfl_xor_sync(0xFFFFFFFFu, l0, 2);
    l1 += __shfl_xor_sync(0xFFFFFFFFu, l1, 1);
    l1 += __shfl_xor_sync(0xFFFFFFFFu, l1, 2);
    float inv0 = __frcp_rn(l0), inv1 = __frcp_rn(l1);
    #pragma unroll
    for (int nt = 0; nt < 8; nt++) {
        int e = (nt << 3) + (tig << 1);
        #pragma unroll
        for (int half = 0; half < 2; half++) {
            float inv = half ? inv1 : inv0;
            int row = r0 + (half << 3);
            float v0 = o[nt][half * 2]     * inv;
            float v1 = o[nt][half * 2 + 1] * inv;
            __nv_bfloat162 hp = __float22bfloat162_rn(make_float2(v0, v1));
            __nv_bfloat162 lp = __float22bfloat162_rn(make_float2(
                v0 - __bfloat162float(hp.x), v1 - __bfloat162float(hp.y)));
            size_t off = ((size_t)(b << 10) + row) * Dd + h * DHh + e;
            *(__nv_bfloat162*)(g_ath + off) = hp;
            *(__nv_bfloat162*)(g_atl + off) = lp;
        }
    }
}

// ---------------------------------------------------------------------------
// Launch: keep fork/join (recovers launch-gap time even when both chains
// saturate the chip).
// ---------------------------------------------------------------------------
extern "C" void kernel_launch(void* const* d_in, const int* in_sizes, int n_in,
                              void* d_out, int out_size) {
    const float*         x      = (const float*)d_in[0];
    const float*         coords = (const float*)d_in[1];
    const unsigned char* mask   = (const unsigned char*)d_in[2];
    const float*         qkv_w  = (const float*)d_in[3];
    const float*         out_w  = (const float*)d_in[4];
    const float*         out_b  = (const float*)d_in[5];
    const float*         w1     = (const float*)d_in[6];
    const float*         b1     = (const float*)d_in[7];
    const float*         w2     = (const float*)d_in[8];
    const float*         b2     = (const float*)d_in[9];
    float*               out    = (float*)d_out;

    static cudaStream_t s2 = nullptr;
    static cudaEvent_t evF = nullptr, evJ = nullptr;
    if (!s2) {
        cudaStreamCreateWithFlags(&s2, cudaStreamNonBlocking);
        cudaEventCreateWithFlags(&evF, cudaEventDisableTiming);
        cudaEventCreateWithFlags(&evJ, cudaEventDisableTiming);
        cudaFuncSetAttribute(k_attn_mma, cudaFuncAttributeMaxDynamicSharedMemorySize, AT_SMEM);
        cudaFuncSetAttribute(k_qkv_mma,  cudaFuncAttributeMaxDynamicSharedMemorySize, GEMM_SMEM);
        cudaFuncSetAttribute(k_out_mma,  cudaFuncAttributeMaxDynamicSharedMemorySize, GEMM_SMEM);
    }

    // fork
    cudaEventRecord(evF, 0);
    cudaStreamWaitEvent(s2, evF, 0);

    // stream s2: bias chain + out_w split (independent of QKV chain)
    k_proj  <<<512, 256, 0, s2>>>(coords, w1);
    k_bias  <<<dim3(32, 32, Bb), 256, 0, s2>>>(b1, w2, b2);
    k_splitT<<<dim3(16, 16), dim3(32, 32), 0, s2>>>(out_w, Dd, Dd, 1);

    // default stream: QKV chain
    k_split_x<<<2048, 256>>>((const float4*)x);
    k_splitT <<<dim3(48, 16), dim3(32, 32)>>>(qkv_w, Dd, 3 * Dd, 0);
    k_qkv_mma<<<dim3(12, 32), 256, GEMM_SMEM>>>();

    // join
    cudaEventRecord(evJ, s2);
    cudaStreamWaitEvent(0, evJ, 0);

    k_attn_mma<<<dim3(8, 32), 256, AT_SMEM>>>(mask);
    k_out_mma <<<dim3(4, 32), 256, GEMM_SMEM>>>(out_b, out);
}